// round 5
// baseline (speedup 1.0000x reference)
#include <cuda_runtime.h>
#include <cuda_bf16.h>
#include <math.h>

#define NB 4
#define NT 512
#define ND 1024
#define NF 4096
#define NE 8
#define NHEAD 16
#define DH 64
#define NTOK 2048
#define CAP 2048
#define NSLOT (NE*CAP)
typedef __nv_bfloat16 bf16;

// ---- static scratch ----
__device__ float g_ln[NTOK*ND];
__device__ float g_scores[(size_t)NB*NHEAD*NT*NT];
__device__ bf16 g_lnH[NTOK*ND],  g_lnL[NTOK*ND];
__device__ bf16 g_qkvH[(size_t)NTOK*3*ND], g_qkvL[(size_t)NTOK*3*ND];
__device__ bf16 g_PH[(size_t)NB*NHEAD*NT*NT], g_PL[(size_t)NB*NHEAD*NT*NT];
__device__ bf16 g_ctxH[NTOK*ND], g_ctxL[NTOK*ND];
__device__ bf16 g_hidH[(size_t)NSLOT*NF], g_hidL[(size_t)NSLOT*NF];
__device__ bf16 g_wqkvH[ND*3*ND], g_wqkvL[ND*3*ND];
__device__ bf16 g_woH[ND*ND],     g_woL[ND*ND];
__device__ bf16 g_w1H[(size_t)NE*ND*NF], g_w1L[(size_t)NE*ND*NF];
__device__ bf16 g_w2H[(size_t)NE*NF*ND], g_w2L[(size_t)NE*NF*ND];
__device__ int   g_slot_token[NSLOT];
__device__ float g_slot_w[NSLOT];
__device__ int   g_count[NE];

__device__ __forceinline__ float gelu_tanh(float x){
    float x3 = x*x*x;
    return 0.5f*x*(1.0f + tanhf(0.7978845608028654f*(x + 0.044715f*x3)));
}
__device__ __forceinline__ void split_pack(float x0, float x1, unsigned& hp, unsigned& lp){
    __nv_bfloat16 h0 = __float2bfloat16_rn(x0);
    __nv_bfloat16 h1 = __float2bfloat16_rn(x1);
    __nv_bfloat16 l0 = __float2bfloat16_rn(x0 - __bfloat162float(h0));
    __nv_bfloat16 l1 = __float2bfloat16_rn(x1 - __bfloat162float(h1));
    hp = ((unsigned)__bfloat16_as_ushort(h1)<<16) | (unsigned)__bfloat16_as_ushort(h0);
    lp = ((unsigned)__bfloat16_as_ushort(l1)<<16) | (unsigned)__bfloat16_as_ushort(l0);
}
__device__ __forceinline__ unsigned sptr(const void* p){
    return (unsigned)__cvta_generic_to_shared(p);
}
#define CPA16(dst,src)    asm volatile("cp.async.cg.shared.global [%0],[%1],16;\n"::"r"(dst),"l"(src):"memory")
#define CPA16Z(dst,src,z) asm volatile("cp.async.cg.shared.global [%0],[%1],16,%2;\n"::"r"(dst),"l"(src),"r"(z):"memory")
#define CPCOMMIT          asm volatile("cp.async.commit_group;\n":::"memory")
__device__ __forceinline__ void cp_wait0(){ asm volatile("cp.async.wait_group 0;\n":::"memory"); }
__device__ __forceinline__ void cp_wait1(){ asm volatile("cp.async.wait_group 1;\n":::"memory"); }

__device__ __forceinline__ void ldsm4(unsigned* r, unsigned a){
    asm volatile("ldmatrix.sync.aligned.m8n8.x4.shared.b16 {%0,%1,%2,%3},[%4];\n"
        :"=r"(r[0]),"=r"(r[1]),"=r"(r[2]),"=r"(r[3]):"r"(a));
}
__device__ __forceinline__ void ldsm4t(unsigned* r, unsigned a){
    asm volatile("ldmatrix.sync.aligned.m8n8.x4.trans.shared.b16 {%0,%1,%2,%3},[%4];\n"
        :"=r"(r[0]),"=r"(r[1]),"=r"(r[2]),"=r"(r[3]):"r"(a));
}
__device__ __forceinline__ void mma_bf16(float* c, const unsigned* a, const unsigned* b){
    asm volatile("mma.sync.aligned.m16n8k16.row.col.f32.bf16.bf16.f32 "
        "{%0,%1,%2,%3}, {%4,%5,%6,%7}, {%8,%9}, {%0,%1,%2,%3};\n"
        : "+f"(c[0]),"+f"(c[1]),"+f"(c[2]),"+f"(c[3])
        : "r"(a[0]),"r"(a[1]),"r"(a[2]),"r"(a[3]), "r"(b[0]),"r"(b[1]));
}

// ================== bf16x3 GEMM core v2 ==================
// BM=128, BK=32, 256 threads (GM*GN=8 warps), warp tile (WM*16)x(WN*8).
// Operands are pre-split bf16 planes. BNK=false: B k-major [K,N]; true: B n-major [N,K].
template<int BN,int GM,int GN,int WM,int WN,bool BNK>
__device__ __forceinline__ void core2(
    const bf16* __restrict__ AH, const bf16* __restrict__ AL, int lda, const int* __restrict__ rmap,
    const bf16* __restrict__ BH, const bf16* __restrict__ BL, int ldb, int K,
    float acc[WM][WN][4])
{
    constexpr int SA  = 40;
    constexpr int SB  = BNK ? 40 : (BN+8);
    constexpr int ASZ = 128*SA;
    constexpr int BSZ = BNK ? (BN*SA) : (32*SB);
    constexpr int STG = 2*ASZ + 2*BSZ;

    extern __shared__ bf16 ds[];

    const int tid=threadIdx.x, lane=tid&31, w=tid>>5;
    const int wm=(w%GM)*(WM*16), wn=(w/GM)*(WN*8);
    const int g=lane>>2, q=lane&3;
    const int lt=lane>>3, lr=lane&7;

    // A staging: 2 chunks/thread/plane
    const int arow0 = tid>>2, arow1 = (tid>>2)+64, akc = (tid&3)*8;
    const bf16 *a0H,*a0L,*a1H,*a1L;
    unsigned az0=16, az1=16;
    if(rmap){
        int t0=rmap[arow0], t1=rmap[arow1];
        if(t0<0){ az0=0; t0=0; }
        if(t1<0){ az1=0; t1=0; }
        a0H = AH + (size_t)t0*lda + akc; a0L = AL + (size_t)t0*lda + akc;
        a1H = AH + (size_t)t1*lda + akc; a1L = AL + (size_t)t1*lda + akc;
    } else {
        a0H = AH + (size_t)arow0*lda + akc; a0L = AL + (size_t)arow0*lda + akc;
        a1H = AH + (size_t)arow1*lda + akc; a1L = AL + (size_t)arow1*lda + akc;
    }
    const unsigned adst0 = arow0*SA + akc, adst1 = arow1*SA + akc;

    // B staging coords
    int brow0, brow1=0, bc;
    if(BNK){ brow0 = tid>>2; brow1 = brow0+64; bc = (tid&3)*8; }
    else if(BN==128){ brow0 = tid>>4; brow1 = brow0+16; bc = (tid&15)*8; }
    else { brow0 = tid>>3; bc = (tid&7)*8; }

    auto stage = [&](int s, int k0){
        bf16* AsH = ds + s*STG;
        bf16* AsL = AsH + ASZ;
        bf16* BsH = AsL + ASZ;
        bf16* BsL = BsH + BSZ;
        CPA16Z(sptr(AsH+adst0), a0H + k0, az0);
        CPA16Z(sptr(AsL+adst0), a0L + k0, az0);
        CPA16Z(sptr(AsH+adst1), a1H + k0, az1);
        CPA16Z(sptr(AsL+adst1), a1L + k0, az1);
        if(BNK){
            CPA16(sptr(BsH + brow0*SB + bc), BH + (size_t)brow0*ldb + k0 + bc);
            CPA16(sptr(BsL + brow0*SB + bc), BL + (size_t)brow0*ldb + k0 + bc);
            CPA16(sptr(BsH + brow1*SB + bc), BH + (size_t)brow1*ldb + k0 + bc);
            CPA16(sptr(BsL + brow1*SB + bc), BL + (size_t)brow1*ldb + k0 + bc);
        } else if(BN==128){
            CPA16(sptr(BsH + brow0*SB + bc), BH + (size_t)(k0+brow0)*ldb + bc);
            CPA16(sptr(BsL + brow0*SB + bc), BL + (size_t)(k0+brow0)*ldb + bc);
            CPA16(sptr(BsH + brow1*SB + bc), BH + (size_t)(k0+brow1)*ldb + bc);
            CPA16(sptr(BsL + brow1*SB + bc), BL + (size_t)(k0+brow1)*ldb + bc);
        } else {
            CPA16(sptr(BsH + brow0*SB + bc), BH + (size_t)(k0+brow0)*ldb + bc);
            CPA16(sptr(BsL + brow0*SB + bc), BL + (size_t)(k0+brow0)*ldb + bc);
        }
    };

    auto compute = [&](int s){
        bf16* AsH = ds + s*STG;
        bf16* AsL = AsH + ASZ;
        bf16* BsH = AsL + ASZ;
        bf16* BsL = BsH + BSZ;
        #pragma unroll
        for(int kk=0;kk<32;kk+=16){
            unsigned aH[WM][4], aL[WM][4], bH[WN][2], bL[WN][2];
            #pragma unroll
            for(int i=0;i<WM;i++){
                unsigned off = (unsigned)((wm + i*16 + (lt&1)*8 + lr)*SA + kk + (lt>>1)*8);
                ldsm4(aH[i], sptr(AsH + off));
                ldsm4(aL[i], sptr(AsL + off));
            }
            if(BNK){
                #pragma unroll
                for(int j=0;j<WN;j++){
                    int n = wn + j*8 + g;
                    bH[j][0]=*(const unsigned*)&BsH[n*SB+kk+q*2]; bH[j][1]=*(const unsigned*)&BsH[n*SB+kk+q*2+8];
                    bL[j][0]=*(const unsigned*)&BsL[n*SB+kk+q*2]; bL[j][1]=*(const unsigned*)&BsL[n*SB+kk+q*2+8];
                }
            } else {
                #pragma unroll
                for(int jp=0;jp<WN/2;jp++){
                    unsigned off = (unsigned)((kk + (lt&1)*8 + lr)*SB + wn + jp*16 + (lt>>1)*8);
                    unsigned rH[4], rL[4];
                    ldsm4t(rH, sptr(BsH + off));
                    ldsm4t(rL, sptr(BsL + off));
                    bH[jp*2][0]=rH[0]; bH[jp*2][1]=rH[1]; bH[jp*2+1][0]=rH[2]; bH[jp*2+1][1]=rH[3];
                    bL[jp*2][0]=rL[0]; bL[jp*2][1]=rL[1]; bL[jp*2+1][0]=rL[2]; bL[jp*2+1][1]=rL[3];
                }
            }
            #pragma unroll
            for(int i=0;i<WM;i++)
                #pragma unroll
                for(int j=0;j<WN;j++){
                    mma_bf16(acc[i][j], aH[i], bH[j]);
                    mma_bf16(acc[i][j], aH[i], bL[j]);
                    mma_bf16(acc[i][j], aL[i], bH[j]);
                }
        }
    };

    const int KT = K/32;
    stage(0, 0); CPCOMMIT;
    int buf = 0;
    for(int s=0;s<KT;s++){
        if(s+1<KT){ stage(buf^1, (s+1)*32); CPCOMMIT; cp_wait1(); }
        else cp_wait0();
        __syncthreads();
        compute(buf);
        __syncthreads();
        buf ^= 1;
    }
}

// smem byte sizes (2 stages)
#define SMEM_KN128 ((2*(2*128*40 + 2*32*136))*2)
#define SMEM_BNK   ((2*(2*128*40 + 2*128*40))*2)
#define SMEM_KN64  ((2*(2*128*40 + 2*32*72))*2)

// ================== GEMM kernels ==================

__global__ __launch_bounds__(256) void tc_gemm_qkv(const float* __restrict__ bias){
    const int m0=blockIdx.y*128, n0=blockIdx.x*128;
    float acc[4][4][4] = {};
    core2<128,2,4,4,4,false>(g_lnH + (size_t)m0*ND, g_lnL + (size_t)m0*ND, ND, nullptr,
                             g_wqkvH + n0, g_wqkvL + n0, 3*ND, ND, acc);
    const int lane=threadIdx.x&31, w=threadIdx.x>>5;
    const int wm=(w&1)*64, wn=(w>>1)*32, g=lane>>2, q=lane&3;
    #pragma unroll
    for(int i=0;i<4;i++)
        #pragma unroll
        for(int j=0;j<4;j++)
            #pragma unroll
            for(int hh=0;hh<2;hh++){
                int row = m0 + wm + i*16 + g + hh*8;
                int col = n0 + wn + j*8 + q*2;
                float v0 = acc[i][j][hh*2]   + bias[col];
                float v1 = acc[i][j][hh*2+1] + bias[col+1];
                unsigned hp,lp; split_pack(v0,v1,hp,lp);
                *(unsigned*)&g_qkvH[(size_t)row*3*ND+col] = hp;
                *(unsigned*)&g_qkvL[(size_t)row*3*ND+col] = lp;
            }
}

__global__ __launch_bounds__(256) void tc_attn_scores(){
    const int bh=blockIdx.z, b=bh>>4, h=bh&15;
    const int m0=blockIdx.y*128, n0=blockIdx.x*128;
    const size_t qb=(size_t)b*NT*3*ND;
    float acc[4][4][4] = {};
    core2<128,2,4,4,4,true>(g_qkvH+qb+(size_t)m0*3*ND+h*DH, g_qkvL+qb+(size_t)m0*3*ND+h*DH, 3*ND, nullptr,
                            g_qkvH+qb+ND+h*DH+(size_t)n0*3*ND, g_qkvL+qb+ND+h*DH+(size_t)n0*3*ND, 3*ND, DH, acc);
    float* S = g_scores + (size_t)bh*NT*NT;
    const int lane=threadIdx.x&31, w=threadIdx.x>>5;
    const int wm=(w&1)*64, wn=(w>>1)*32, g=lane>>2, q=lane&3;
    #pragma unroll
    for(int i=0;i<4;i++)
        #pragma unroll
        for(int j=0;j<4;j++)
            #pragma unroll
            for(int hh=0;hh<2;hh++){
                int row = m0 + wm + i*16 + g + hh*8;
                int col = n0 + wn + j*8 + q*2;
                float2 o; o.x = acc[i][j][hh*2]*0.125f; o.y = acc[i][j][hh*2+1]*0.125f;
                *(float2*)&S[(size_t)row*NT+col] = o;
            }
}

__global__ __launch_bounds__(256) void tc_attn_ctx(){
    const int bh=blockIdx.z, b=bh>>4, h=bh&15;
    const int m0=blockIdx.y*128;
    const size_t qb=(size_t)b*NT*3*ND;
    float acc[4][2][4] = {};
    core2<64,2,4,4,2,false>(g_PH + (size_t)bh*NT*NT + (size_t)m0*NT, g_PL + (size_t)bh*NT*NT + (size_t)m0*NT, NT, nullptr,
                            g_qkvH+qb+2*ND+h*DH, g_qkvL+qb+2*ND+h*DH, 3*ND, NT, acc);
    const int lane=threadIdx.x&31, w=threadIdx.x>>5;
    const int wm=(w&1)*64, wn=(w>>1)*16, g=lane>>2, q=lane&3;
    #pragma unroll
    for(int i=0;i<4;i++)
        #pragma unroll
        for(int j=0;j<2;j++)
            #pragma unroll
            for(int hh=0;hh<2;hh++){
                int row = m0 + wm + i*16 + g + hh*8;
                int col = wn + j*8 + q*2;
                unsigned hp,lp; split_pack(acc[i][j][hh*2], acc[i][j][hh*2+1], hp, lp);
                size_t idx = (size_t)(b*NT+row)*ND + h*DH + col;
                *(unsigned*)&g_ctxH[idx] = hp;
                *(unsigned*)&g_ctxL[idx] = lp;
            }
}

__global__ __launch_bounds__(256) void tc_gemm_o(
    const float* __restrict__ bias, const float* __restrict__ res, float* __restrict__ out){
    const int m0=blockIdx.y*128, n0=blockIdx.x*128;
    float acc[4][4][4] = {};
    core2<128,2,4,4,4,false>(g_ctxH + (size_t)m0*ND, g_ctxL + (size_t)m0*ND, ND, nullptr,
                             g_woH + n0, g_woL + n0, ND, ND, acc);
    const int lane=threadIdx.x&31, w=threadIdx.x>>5;
    const int wm=(w&1)*64, wn=(w>>1)*32, g=lane>>2, q=lane&3;
    #pragma unroll
    for(int i=0;i<4;i++)
        #pragma unroll
        for(int j=0;j<4;j++)
            #pragma unroll
            for(int hh=0;hh<2;hh++){
                int row = m0 + wm + i*16 + g + hh*8;
                int col = n0 + wn + j*8 + q*2;
                float2 r = *(const float2*)&res[(size_t)row*ND+col];
                float2 o;
                o.x = acc[i][j][hh*2]   + bias[col]   + r.x;
                o.y = acc[i][j][hh*2+1] + bias[col+1] + r.y;
                *(float2*)&out[(size_t)row*ND+col] = o;
            }
}

__global__ __launch_bounds__(256) void tc_moe_gemm1(const float* __restrict__ b1){
    const int e = blockIdx.y >> 4;
    const int rt = blockIdx.y & 15;
    const int cnt = g_count[e];
    if(rt*128 >= cnt) return;
    const int m0 = rt*128, n0 = blockIdx.x*128;
    float acc[4][4][4] = {};
    core2<128,2,4,4,4,false>(g_lnH, g_lnL, ND, &g_slot_token[e*CAP + m0],
                             g_w1H + (size_t)e*ND*NF + n0, g_w1L + (size_t)e*ND*NF + n0, NF, ND, acc);
    const int lane=threadIdx.x&31, w=threadIdx.x>>5;
    const int wm=(w&1)*64, wn=(w>>1)*32, g=lane>>2, q=lane&3;
    #pragma unroll
    for(int i=0;i<4;i++)
        #pragma unroll
        for(int j=0;j<4;j++)
            #pragma unroll
            for(int hh=0;hh<2;hh++){
                int sl  = m0 + wm + i*16 + g + hh*8;
                int col = n0 + wn + j*8 + q*2;
                float v0 = gelu_tanh(acc[i][j][hh*2]   + b1[e*NF + col]);
                float v1 = gelu_tanh(acc[i][j][hh*2+1] + b1[e*NF + col+1]);
                unsigned hp,lp; split_pack(v0,v1,hp,lp);
                size_t idx = (size_t)(e*CAP+sl)*NF + col;
                *(unsigned*)&g_hidH[idx] = hp;
                *(unsigned*)&g_hidL[idx] = lp;
            }
}

__global__ __launch_bounds__(256) void tc_moe_gemm2(const float* __restrict__ b2, float* __restrict__ out){
    const int e = blockIdx.y >> 4;
    const int rt = blockIdx.y & 15;
    const int cnt = g_count[e];
    if(rt*128 >= cnt) return;
    const int m0 = rt*128, n0 = blockIdx.x*128;
    float acc[4][4][4] = {};
    core2<128,2,4,4,4,false>(g_hidH + (size_t)(e*CAP + m0)*NF, g_hidL + (size_t)(e*CAP + m0)*NF, NF, nullptr,
                             g_w2H + (size_t)e*NF*ND + n0, g_w2L + (size_t)e*NF*ND + n0, ND, NF, acc);
    const int lane=threadIdx.x&31, w=threadIdx.x>>5;
    const int wm=(w&1)*64, wn=(w>>1)*32, g=lane>>2, q=lane&3;
    #pragma unroll
    for(int i=0;i<4;i++)
        #pragma unroll
        for(int j=0;j<4;j++)
            #pragma unroll
            for(int hh=0;hh<2;hh++){
                int sl = m0 + wm + i*16 + g + hh*8;
                if(sl < cnt){
                    int tok = g_slot_token[e*CAP + sl];
                    float ws = g_slot_w[e*CAP + sl];
                    int col = n0 + wn + j*8 + q*2;
                    atomicAdd(&out[(size_t)tok*ND + col],   ws*(acc[i][j][hh*2]   + b2[e*ND + col]));
                    atomicAdd(&out[(size_t)tok*ND + col+1], ws*(acc[i][j][hh*2+1] + b2[e*ND + col+1]));
                }
            }
}

// ================== auxiliary kernels ==================

__global__ void conv_split_kernel(const float* __restrict__ src, bf16* __restrict__ H, bf16* __restrict__ L){
    size_t i = ((size_t)blockIdx.x*256 + threadIdx.x)*4;
    float4 v = *(const float4*)(src + i);
    unsigned h0,l0,h1,l1;
    split_pack(v.x,v.y,h0,l0);
    split_pack(v.z,v.w,h1,l1);
    *(uint2*)&H[i] = make_uint2(h0,h1);
    *(uint2*)&L[i] = make_uint2(l0,l1);
}

__global__ void ln_kernel(const float* __restrict__ x,
                          const float* __restrict__ w,
                          const float* __restrict__ b,
                          float* __restrict__ y, bf16* __restrict__ H, bf16* __restrict__ L)
{
    int row = blockIdx.x;
    int t = threadIdx.x;
    float4 v = *(const float4*)(x + (size_t)row*ND + t*4);
    float s = v.x+v.y+v.z+v.w;
    __shared__ float red[256];
    red[t] = s; __syncthreads();
    for(int o=128;o>0;o>>=1){ if(t<o) red[t]+=red[t+o]; __syncthreads(); }
    float mu = red[0]*(1.0f/ND);
    __syncthreads();
    float d0=v.x-mu, d1=v.y-mu, d2=v.z-mu, d3=v.w-mu;
    red[t] = d0*d0+d1*d1+d2*d2+d3*d3; __syncthreads();
    for(int o=128;o>0;o>>=1){ if(t<o) red[t]+=red[t+o]; __syncthreads(); }
    float rstd = rsqrtf(red[0]*(1.0f/ND) + 1e-5f);
    float4 wv = *(const float4*)(w + t*4);
    float4 bv = *(const float4*)(b + t*4);
    float4 o;
    o.x = d0*rstd*wv.x + bv.x;
    o.y = d1*rstd*wv.y + bv.y;
    o.z = d2*rstd*wv.z + bv.z;
    o.w = d3*rstd*wv.w + bv.w;
    *(float4*)(y + (size_t)row*ND + t*4) = o;
    unsigned h0,l0,h1,l1;
    split_pack(o.x,o.y,h0,l0);
    split_pack(o.z,o.w,h1,l1);
    *(uint2*)&H[(size_t)row*ND + t*4] = make_uint2(h0,h1);
    *(uint2*)&L[(size_t)row*ND + t*4] = make_uint2(l0,l1);
}

__global__ void softmax_kernel()
{
    int wrow = blockIdx.x*8 + (threadIdx.x>>5);
    int lane = threadIdx.x & 31;
    const float* r = g_scores + (size_t)wrow*NT;
    float v[16];
    #pragma unroll
    for(int ii=0;ii<4;ii++)
        *(float4*)&v[ii*4] = *(const float4*)&r[lane*16 + ii*4];
    float mx = -1e30f;
    #pragma unroll
    for(int i=0;i<16;i++) mx = fmaxf(mx, v[i]);
    #pragma unroll
    for(int o=16;o>0;o>>=1) mx = fmaxf(mx, __shfl_xor_sync(0xffffffffu, mx, o));
    float s = 0.f;
    #pragma unroll
    for(int i=0;i<16;i++){ v[i] = expf(v[i]-mx); s += v[i]; }
    #pragma unroll
    for(int o=16;o>0;o>>=1) s += __shfl_xor_sync(0xffffffffu, s, o);
    float inv = 1.0f/s;
    size_t base = (size_t)wrow*NT + lane*16;
    #pragma unroll
    for(int ii=0;ii<8;ii++){
        unsigned hp,lp;
        split_pack(v[2*ii]*inv, v[2*ii+1]*inv, hp, lp);
        *(unsigned*)&g_PH[base + 2*ii] = hp;
        *(unsigned*)&g_PL[base + 2*ii] = lp;
    }
}

__global__ void moe_reset_kernel()
{
    int i = blockIdx.x*256 + threadIdx.x;
    if(i < NSLOT) g_slot_token[i] = -1;
    if(i < NE) g_count[i] = 0;
}

__global__ void gate_kernel(const float* __restrict__ wg)
{
    int token = blockIdx.x*8 + (threadIdx.x>>5);
    int lane = threadIdx.x & 31;
    const float* t = g_ln + (size_t)token*ND;
    float acc[NE] = {};
    for(int d=lane; d<ND; d+=32){
        float td = t[d];
        const float* w = wg + d*NE;
        #pragma unroll
        for(int e=0;e<NE;e++) acc[e] += td*w[e];
    }
    #pragma unroll
    for(int e=0;e<NE;e++)
        #pragma unroll
        for(int o=16;o>0;o>>=1) acc[e] += __shfl_xor_sync(0xffffffffu, acc[e], o);
    if(lane==0){
        float mx = -1e30f;
        #pragma unroll
        for(int e=0;e<NE;e++) mx = fmaxf(mx, acc[e]);
        float p[NE], s=0.f;
        #pragma unroll
        for(int e=0;e<NE;e++){ p[e] = expf(acc[e]-mx); s += p[e]; }
        float inv = 1.0f/s;
        #pragma unroll
        for(int e=0;e<NE;e++) p[e] *= inv;
        int e0 = 0;
        #pragma unroll
        for(int e=1;e<NE;e++) if(p[e] > p[e0]) e0 = e;
        int e1 = (e0==0) ? 1 : 0;
        #pragma unroll
        for(int e=0;e<NE;e++) if(e!=e0 && p[e] > p[e1]) e1 = e;
        float w0 = p[e0], w1 = p[e1];
        float rn = 1.0f/(w0+w1);
        w0 *= rn; w1 *= rn;
        int p0 = atomicAdd(&g_count[e0], 1);
        g_slot_token[e0*CAP + p0] = token; g_slot_w[e0*CAP + p0] = w0;
        int p1 = atomicAdd(&g_count[e1], 1);
        g_slot_token[e1*CAP + p1] = token; g_slot_w[e1*CAP + p1] = w1;
    }
}

// ================== launch ==================
extern "C" void kernel_launch(void* const* d_in, const int* in_sizes, int n_in,
                              void* d_out, int out_size)
{
    const float* x    = (const float*)d_in[0];
    const float* ln1w = (const float*)d_in[1];
    const float* ln1b = (const float*)d_in[2];
    const float* ln2w = (const float*)d_in[3];
    const float* ln2b = (const float*)d_in[4];
    const float* wqkv = (const float*)d_in[5];
    const float* bqkv = (const float*)d_in[6];
    const float* wo   = (const float*)d_in[7];
    const float* bo   = (const float*)d_in[8];
    const float* wg   = (const float*)d_in[9];
    const float* w1   = (const float*)d_in[10];
    const float* b1   = (const float*)d_in[11];
    const float* w2   = (const float*)d_in[12];
    const float* b2   = (const float*)d_in[13];
    float* out = (float*)d_out;

    float *p_ln;
    bf16 *p_lnH, *p_lnL, *p_wqkvH, *p_wqkvL, *p_woH, *p_woL, *p_w1H, *p_w1L, *p_w2H, *p_w2L;
    cudaGetSymbolAddress((void**)&p_ln,    g_ln);
    cudaGetSymbolAddress((void**)&p_lnH,   g_lnH);
    cudaGetSymbolAddress((void**)&p_lnL,   g_lnL);
    cudaGetSymbolAddress((void**)&p_wqkvH, g_wqkvH);
    cudaGetSymbolAddress((void**)&p_wqkvL, g_wqkvL);
    cudaGetSymbolAddress((void**)&p_woH,   g_woH);
    cudaGetSymbolAddress((void**)&p_woL,   g_woL);
    cudaGetSymbolAddress((void**)&p_w1H,   g_w1H);
    cudaGetSymbolAddress((void**)&p_w1L,   g_w1L);
    cudaGetSymbolAddress((void**)&p_w2H,   g_w2H);
    cudaGetSymbolAddress((void**)&p_w2L,   g_w2L);

    cudaFuncSetAttribute(tc_gemm_qkv,    cudaFuncAttributeMaxDynamicSharedMemorySize, SMEM_KN128);
    cudaFuncSetAttribute(tc_gemm_o,      cudaFuncAttributeMaxDynamicSharedMemorySize, SMEM_KN128);
    cudaFuncSetAttribute(tc_moe_gemm1,   cudaFuncAttributeMaxDynamicSharedMemorySize, SMEM_KN128);
    cudaFuncSetAttribute(tc_moe_gemm2,   cudaFuncAttributeMaxDynamicSharedMemorySize, SMEM_KN128);
    cudaFuncSetAttribute(tc_attn_scores, cudaFuncAttributeMaxDynamicSharedMemorySize, SMEM_BNK);
    cudaFuncSetAttribute(tc_attn_ctx,    cudaFuncAttributeMaxDynamicSharedMemorySize, SMEM_KN64);

    // weight pre-splits
    conv_split_kernel<<<ND*3*ND/1024, 256>>>(wqkv, p_wqkvH, p_wqkvL);
    conv_split_kernel<<<ND*ND/1024,   256>>>(wo,   p_woH,   p_woL);
    conv_split_kernel<<<NE*ND*NF/1024,256>>>(w1,   p_w1H,   p_w1L);
    conv_split_kernel<<<NE*NF*ND/1024,256>>>(w2,   p_w2H,   p_w2L);

    ln_kernel<<<NTOK, 256>>>(x, ln1w, ln1b, p_ln, p_lnH, p_lnL);
    tc_gemm_qkv<<<dim3(3*ND/128, NTOK/128), 256, SMEM_KN128>>>(bqkv);
    tc_attn_scores<<<dim3(NT/128, NT/128, NB*NHEAD), 256, SMEM_BNK>>>();
    softmax_kernel<<<(NB*NHEAD*NT)/8, 256>>>();
    tc_attn_ctx<<<dim3(1, NT/128, NB*NHEAD), 256, SMEM_KN64>>>();
    tc_gemm_o<<<dim3(ND/128, NTOK/128), 256, SMEM_KN128>>>(bo, x, out);
    ln_kernel<<<NTOK, 256>>>(out, ln2w, ln2b, p_ln, p_lnH, p_lnL);
    moe_reset_kernel<<<NSLOT/256, 256>>>();
    gate_kernel<<<NTOK/8, 256>>>(wg);
    tc_moe_gemm1<<<dim3(NF/128, NE*16), 256, SMEM_KN128>>>(b1);
    tc_moe_gemm2<<<dim3(ND/128, NE*16), 256, SMEM_KN128>>>(b2, out);
}

// round 8
// speedup vs baseline: 1.4202x; 1.4202x over previous
#include <cuda_runtime.h>
#include <cuda_fp16.h>
#include <math.h>

#define NB 4
#define NT 512
#define ND 1024
#define NF 4096
#define NE 8
#define NHEAD 16
#define DH 64
#define NTOK (NB*NT)          // 2048
#define CAP 2048
#define NSLOT (NE*CAP)

// ---- static scratch ----
__device__ float g_ln[NTOK*ND];
__device__ float g_qkv[(size_t)NTOK*3*ND];
__device__ float g_scores[(size_t)NB*NHEAD*NT*NT];
__device__ float g_ctx[(size_t)NTOK*ND];
__device__ float g_hidden[(size_t)NSLOT*NF];
__device__ int   g_slot_token[NSLOT];
__device__ float g_slot_w[NSLOT];
__device__ int   g_count[NE];

__device__ __forceinline__ float gelu_tanh(float x){
    float x3 = x*x*x;
    return 0.5f*x*(1.0f + tanhf(0.7978845608028654f*(x + 0.044715f*x3)));
}

// ---- fp16 split helpers ----
// A operand: x = hi + lo, both fp16 (lo captures the next 10 bits).
__device__ __forceinline__ void splitA_pack(float x0, float x1, unsigned& hp, unsigned& lp){
    __half h0 = __float2half_rn(x0);
    __half h1 = __float2half_rn(x1);
    __half l0 = __float2half_rn(x0 - __half2float(h0));
    __half l1 = __float2half_rn(x1 - __half2float(h1));
    hp = ((unsigned)__half_as_ushort(h1)<<16) | (unsigned)__half_as_ushort(h0);
    lp = ((unsigned)__half_as_ushort(l1)<<16) | (unsigned)__half_as_ushort(l0);
}
// B operand: single rounded fp16 plane.
__device__ __forceinline__ unsigned roundB_pack(float x0, float x1){
    return ((unsigned)__half_as_ushort(__float2half_rn(x1))<<16)
         |  (unsigned)__half_as_ushort(__float2half_rn(x0));
}

__device__ __forceinline__ void mma_f16(float* c, const unsigned* a, const unsigned* b){
    asm volatile("mma.sync.aligned.m16n8k16.row.col.f32.f16.f16.f32 "
        "{%0,%1,%2,%3}, {%4,%5,%6,%7}, {%8,%9}, {%0,%1,%2,%3};\n"
        : "+f"(c[0]),"+f"(c[1]),"+f"(c[2]),"+f"(c[3])
        : "r"(a[0]),"r"(a[1]),"r"(a[2]),"r"(a[3]), "r"(b[0]),"r"(b[1]));
}

// ================== fp16x2 GEMM core ==================
// BM=128 fixed. Block = GM*GN warps (=8 -> 256 threads).
// A: fp32 row-major [M,K] (pre-offset to block row, or rmap gather), split hi/lo in smem.
// B: fp32; if !BNK row-major [K,N] (pre-offset by n0); if BNK n-major [N,K] (pre-offset by n0 rows).
//    Single rounded fp16 plane in smem.
template<int BN,int GM,int GN,int WM,int WN,bool BNK>
__device__ __forceinline__ void core_f16x2(
    const float* __restrict__ A, int lda, const int* __restrict__ rmap,
    const float* __restrict__ Bm, int ldb, int K,
    float acc[WM][WN][4])
{
    constexpr int SA  = 24;               // A smem stride (fp16 elems)
    constexpr int SBk = BN + 8;           // B kn-layout stride
    constexpr int SBn = 24;               // B nk-layout stride
    constexpr int BSZ = BNK ? BN*SBn : 16*SBk;

    __shared__ __align__(16) __half AsH[128*SA], AsL[128*SA];
    __shared__ __align__(16) __half Bs[BSZ];

    const int tid  = threadIdx.x;
    const int lane = tid & 31, w = tid >> 5;
    const int wm = (w % GM)*(WM*16);
    const int wn = (w / GM)*(WN*8);
    const int g = lane>>2, q = lane&3;

    // ---- A staging coords: row = tid>>1, k-offset = (tid&1)*8 ----
    const int ar = tid>>1, ak = (tid&1)*8;
    const float* Ap = nullptr;
    if(rmap){ int tok = rmap[ar]; if(tok>=0) Ap = A + (size_t)tok*lda + ak; }
    else      Ap = A + (size_t)ar*lda + ak;
    const int aoff = ar*SA + ak;

    // ---- B staging coords ----
    const float* Bp;
    int boff;
    if(BNK){
        const int bnr = tid>>1, bk = (tid&1)*8;
        Bp = Bm + (size_t)bnr*ldb + bk;
        boff = bnr*SBn + bk;
    } else if(BN==128){
        const int bkr = tid>>4, bn = (tid&15)*8;
        Bp = Bm + (size_t)bkr*ldb + bn;
        boff = bkr*SBk + bn;
    } else { // BN==64
        const int bkr = tid>>4, bn = (tid&15)*4;
        Bp = Bm + (size_t)bkr*ldb + bn;
        boff = bkr*SBk + bn;
    }

    for(int k0=0;k0<K;k0+=16){
        // ---- stage A (128x16, split hi/lo) ----
        {
            float4 v0, v1;
            if(Ap){ v0 = *(const float4*)(Ap + k0); v1 = *(const float4*)(Ap + k0 + 4); }
            else  { v0 = make_float4(0,0,0,0); v1 = v0; }
            unsigned h,l;
            splitA_pack(v0.x,v0.y,h,l); *(unsigned*)&AsH[aoff  ]=h; *(unsigned*)&AsL[aoff  ]=l;
            splitA_pack(v0.z,v0.w,h,l); *(unsigned*)&AsH[aoff+2]=h; *(unsigned*)&AsL[aoff+2]=l;
            splitA_pack(v1.x,v1.y,h,l); *(unsigned*)&AsH[aoff+4]=h; *(unsigned*)&AsL[aoff+4]=l;
            splitA_pack(v1.z,v1.w,h,l); *(unsigned*)&AsH[aoff+6]=h; *(unsigned*)&AsL[aoff+6]=l;
        }
        // ---- stage B (16xBN or BNx16, single rounded plane) ----
        {
            if(BNK){
                float4 u0 = *(const float4*)(Bp + k0);
                float4 u1 = *(const float4*)(Bp + k0 + 4);
                *(unsigned*)&Bs[boff  ] = roundB_pack(u0.x,u0.y);
                *(unsigned*)&Bs[boff+2] = roundB_pack(u0.z,u0.w);
                *(unsigned*)&Bs[boff+4] = roundB_pack(u1.x,u1.y);
                *(unsigned*)&Bs[boff+6] = roundB_pack(u1.z,u1.w);
            } else if(BN==128){
                float4 u0 = *(const float4*)(Bp + (size_t)k0*ldb);
                float4 u1 = *(const float4*)(Bp + (size_t)k0*ldb + 4);
                *(unsigned*)&Bs[boff  ] = roundB_pack(u0.x,u0.y);
                *(unsigned*)&Bs[boff+2] = roundB_pack(u0.z,u0.w);
                *(unsigned*)&Bs[boff+4] = roundB_pack(u1.x,u1.y);
                *(unsigned*)&Bs[boff+6] = roundB_pack(u1.z,u1.w);
            } else {
                float4 u0 = *(const float4*)(Bp + (size_t)k0*ldb);
                *(unsigned*)&Bs[boff  ] = roundB_pack(u0.x,u0.y);
                *(unsigned*)&Bs[boff+2] = roundB_pack(u0.z,u0.w);
            }
        }
        __syncthreads();

        // ---- fragments ----
        unsigned aH[WM][4], aL[WM][4], bR[WN][2];
        #pragma unroll
        for(int i=0;i<WM;i++){
            int r0 = (wm + i*16 + g    )*SA + q*2;
            int r1 = (wm + i*16 + g + 8)*SA + q*2;
            aH[i][0]=*(const unsigned*)&AsH[r0];   aH[i][1]=*(const unsigned*)&AsH[r1];
            aH[i][2]=*(const unsigned*)&AsH[r0+8]; aH[i][3]=*(const unsigned*)&AsH[r1+8];
            aL[i][0]=*(const unsigned*)&AsL[r0];   aL[i][1]=*(const unsigned*)&AsL[r1];
            aL[i][2]=*(const unsigned*)&AsL[r0+8]; aL[i][3]=*(const unsigned*)&AsL[r1+8];
        }
        #pragma unroll
        for(int j=0;j<WN;j++){
            int n = wn + j*8 + g;
            if(BNK){
                int o = n*SBn + q*2;
                bR[j][0]=*(const unsigned*)&Bs[o]; bR[j][1]=*(const unsigned*)&Bs[o+8];
            } else {
                const unsigned short* ph = (const unsigned short*)&Bs[(q*2)*SBk + n];
                bR[j][0] = (unsigned)ph[0]      | ((unsigned)ph[SBk]  <<16);
                bR[j][1] = (unsigned)ph[8*SBk]  | ((unsigned)ph[9*SBk]<<16);
            }
        }
        #pragma unroll
        for(int i=0;i<WM;i++)
            #pragma unroll
            for(int j=0;j<WN;j++){
                mma_f16(acc[i][j], aH[i], bR[j]);
                mma_f16(acc[i][j], aL[i], bR[j]);
            }
        __syncthreads();
    }
}

// ================== GEMM kernels ==================

// C = A@B + bias (+res)
__global__ __launch_bounds__(256) void tc_gemm_bias(
    const float* __restrict__ A, int lda,
    const float* __restrict__ B, int ldb,
    const float* __restrict__ bias,
    const float* __restrict__ res,
    float* __restrict__ C, int ldc, int K)
{
    const int m0 = blockIdx.y*128, n0 = blockIdx.x*128;
    float acc[4][4][4] = {};
    core_f16x2<128,2,4,4,4,false>(A + (size_t)m0*lda, lda, nullptr, B + n0, ldb, K, acc);
    const int lane = threadIdx.x&31, w = threadIdx.x>>5;
    const int wm = (w&1)*64, wn = (w>>1)*32;
    const int g = lane>>2, q = lane&3;
    #pragma unroll
    for(int i=0;i<4;i++)
        #pragma unroll
        for(int j=0;j<4;j++)
            #pragma unroll
            for(int hh=0;hh<2;hh++){
                int row = m0 + wm + i*16 + g + hh*8;
                int col = n0 + wn + j*8 + q*2;
                float v0 = acc[i][j][hh*2]   + bias[col];
                float v1 = acc[i][j][hh*2+1] + bias[col+1];
                if(res){
                    float2 r = *(const float2*)&res[(size_t)row*ldc+col];
                    v0 += r.x; v1 += r.y;
                }
                float2 o; o.x=v0; o.y=v1;
                *(float2*)&C[(size_t)row*ldc+col] = o;
            }
}

// scores = Q @ K^T / 8  per (b,h)
__global__ __launch_bounds__(256) void tc_attn_scores()
{
    const int bh = blockIdx.z;
    const int b = bh>>4, h = bh&15;
    const float* Q  = g_qkv + (size_t)b*NT*3*ND + h*DH;
    const float* Kp = g_qkv + (size_t)b*NT*3*ND + ND + h*DH;
    float* S = g_scores + (size_t)bh*NT*NT;
    const int m0 = blockIdx.y*128, n0 = blockIdx.x*128;
    float acc[4][4][4] = {};
    core_f16x2<128,2,4,4,4,true>(Q + (size_t)m0*(3*ND), 3*ND, nullptr,
                                 Kp + (size_t)n0*(3*ND), 3*ND, DH, acc);
    const int lane = threadIdx.x&31, w = threadIdx.x>>5;
    const int wm = (w&1)*64, wn = (w>>1)*32;
    const int g = lane>>2, q = lane&3;
    #pragma unroll
    for(int i=0;i<4;i++)
        #pragma unroll
        for(int j=0;j<4;j++)
            #pragma unroll
            for(int hh=0;hh<2;hh++){
                int row = m0 + wm + i*16 + g + hh*8;
                int col = n0 + wn + j*8 + q*2;
                float2 o;
                o.x = acc[i][j][hh*2]  *0.125f;
                o.y = acc[i][j][hh*2+1]*0.125f;
                *(float2*)&S[(size_t)row*NT+col] = o;
            }
}

// ctx = P @ V per (b,h): M=512, N=64, K=512
__global__ __launch_bounds__(256) void tc_attn_ctx()
{
    const int bh = blockIdx.z;
    const int b = bh>>4, h = bh&15;
    const float* P = g_scores + (size_t)bh*NT*NT;
    const float* V = g_qkv + (size_t)b*NT*3*ND + 2*ND + h*DH;
    const int m0 = blockIdx.y*128;
    float acc[2][4][4] = {};
    core_f16x2<64,4,2,2,4,false>(P + (size_t)m0*NT, NT, nullptr, V, 3*ND, NT, acc);
    const int lane = threadIdx.x&31, w = threadIdx.x>>5;
    const int wm = (w&3)*32, wn = (w>>2)*32;
    const int g = lane>>2, q = lane&3;
    #pragma unroll
    for(int i=0;i<2;i++)
        #pragma unroll
        for(int j=0;j<4;j++)
            #pragma unroll
            for(int hh=0;hh<2;hh++){
                int row = m0 + wm + i*16 + g + hh*8;
                int col = wn + j*8 + q*2;
                float2 o;
                o.x = acc[i][j][hh*2];
                o.y = acc[i][j][hh*2+1];
                *(float2*)&g_ctx[(size_t)(b*NT+row)*ND + h*DH + col] = o;
            }
}

// MoE GEMM1: hidden = gelu(gather(ln2) @ w1[e] + b1[e])
__global__ __launch_bounds__(256) void tc_moe_gemm1(
    const float* __restrict__ w1, const float* __restrict__ b1)
{
    const int e = blockIdx.y >> 4;
    const int rt = blockIdx.y & 15;
    const int cnt = g_count[e];
    if(rt*128 >= cnt) return;
    const int m0 = rt*128, n0 = blockIdx.x*128;
    float acc[4][4][4] = {};
    core_f16x2<128,2,4,4,4,false>(g_ln, ND, &g_slot_token[e*CAP + m0],
                                  w1 + (size_t)e*ND*NF + n0, NF, ND, acc);
    const int lane = threadIdx.x&31, w = threadIdx.x>>5;
    const int wm = (w&1)*64, wn = (w>>1)*32;
    const int g = lane>>2, q = lane&3;
    #pragma unroll
    for(int i=0;i<4;i++)
        #pragma unroll
        for(int j=0;j<4;j++)
            #pragma unroll
            for(int hh=0;hh<2;hh++){
                int sl  = m0 + wm + i*16 + g + hh*8;
                int col = n0 + wn + j*8 + q*2;
                float v0 = gelu_tanh(acc[i][j][hh*2]   + b1[e*NF + col]);
                float v1 = gelu_tanh(acc[i][j][hh*2+1] + b1[e*NF + col+1]);
                float2 o; o.x=v0; o.y=v1;
                *(float2*)&g_hidden[(size_t)(e*CAP+sl)*NF + col] = o;
            }
}

// MoE GEMM2: out += w_slot * (hidden @ w2[e] + b2[e])
__global__ __launch_bounds__(256) void tc_moe_gemm2(
    const float* __restrict__ w2, const float* __restrict__ b2,
    float* __restrict__ out)
{
    const int e = blockIdx.y >> 4;
    const int rt = blockIdx.y & 15;
    const int cnt = g_count[e];
    if(rt*128 >= cnt) return;
    const int m0 = rt*128, n0 = blockIdx.x*128;
    float acc[4][4][4] = {};
    core_f16x2<128,2,4,4,4,false>(g_hidden + (size_t)(e*CAP + m0)*NF, NF, nullptr,
                                  w2 + (size_t)e*NF*ND + n0, ND, NF, acc);
    const int lane = threadIdx.x&31, w = threadIdx.x>>5;
    const int wm = (w&1)*64, wn = (w>>1)*32;
    const int g = lane>>2, q = lane&3;
    #pragma unroll
    for(int i=0;i<4;i++)
        #pragma unroll
        for(int j=0;j<4;j++)
            #pragma unroll
            for(int hh=0;hh<2;hh++){
                int sl  = m0 + wm + i*16 + g + hh*8;
                if(sl < cnt){
                    int tok = g_slot_token[e*CAP + sl];
                    float ws = g_slot_w[e*CAP + sl];
                    int col = n0 + wn + j*8 + q*2;
                    atomicAdd(&out[(size_t)tok*ND + col],   ws*(acc[i][j][hh*2]   + b2[e*ND + col]));
                    atomicAdd(&out[(size_t)tok*ND + col+1], ws*(acc[i][j][hh*2+1] + b2[e*ND + col+1]));
                }
            }
}

// ================== non-GEMM kernels ==================

__global__ void ln_kernel(const float* __restrict__ x,
                          const float* __restrict__ w,
                          const float* __restrict__ b,
                          float* __restrict__ y)
{
    int row = blockIdx.x;
    int t = threadIdx.x;
    float4 v = *(const float4*)(x + (size_t)row*ND + t*4);
    float s = v.x+v.y+v.z+v.w;
    __shared__ float red[256];
    red[t] = s; __syncthreads();
    for(int o=128;o>0;o>>=1){ if(t<o) red[t]+=red[t+o]; __syncthreads(); }
    float mu = red[0]*(1.0f/ND);
    __syncthreads();
    float d0=v.x-mu, d1=v.y-mu, d2=v.z-mu, d3=v.w-mu;
    red[t] = d0*d0+d1*d1+d2*d2+d3*d3; __syncthreads();
    for(int o=128;o>0;o>>=1){ if(t<o) red[t]+=red[t+o]; __syncthreads(); }
    float rstd = rsqrtf(red[0]*(1.0f/ND) + 1e-5f);
    float4 wv = *(const float4*)(w + t*4);
    float4 bv = *(const float4*)(b + t*4);
    float4 o;
    o.x = d0*rstd*wv.x + bv.x;
    o.y = d1*rstd*wv.y + bv.y;
    o.z = d2*rstd*wv.z + bv.z;
    o.w = d3*rstd*wv.w + bv.w;
    *(float4*)(y + (size_t)row*ND + t*4) = o;
}

__global__ void softmax_kernel()
{
    int wrow = blockIdx.x*8 + (threadIdx.x>>5);
    int lane = threadIdx.x & 31;
    float* r = g_scores + (size_t)wrow*NT;
    float v[16];
    #pragma unroll
    for(int ii=0;ii<4;ii++)
        *(float4*)&v[ii*4] = *(const float4*)&r[lane*16 + ii*4];
    float mx = -1e30f;
    #pragma unroll
    for(int i=0;i<16;i++) mx = fmaxf(mx, v[i]);
    #pragma unroll
    for(int o=16;o>0;o>>=1) mx = fmaxf(mx, __shfl_xor_sync(0xffffffffu, mx, o));
    float s = 0.f;
    #pragma unroll
    for(int i=0;i<16;i++){ v[i] = expf(v[i]-mx); s += v[i]; }
    #pragma unroll
    for(int o=16;o>0;o>>=1) s += __shfl_xor_sync(0xffffffffu, s, o);
    float inv = 1.0f/s;
    #pragma unroll
    for(int ii=0;ii<4;ii++){
        float4 o;
        o.x = v[ii*4]*inv; o.y = v[ii*4+1]*inv; o.z = v[ii*4+2]*inv; o.w = v[ii*4+3]*inv;
        *(float4*)&r[lane*16 + ii*4] = o;
    }
}

__global__ void moe_reset_kernel()
{
    int i = blockIdx.x*256 + threadIdx.x;
    if(i < NSLOT) g_slot_token[i] = -1;
    if(i < NE) g_count[i] = 0;
}

__global__ void gate_kernel(const float* __restrict__ wg)
{
    int token = blockIdx.x*8 + (threadIdx.x>>5);
    int lane = threadIdx.x & 31;
    const float* t = g_ln + (size_t)token*ND;
    float acc[NE] = {};
    for(int d=lane; d<ND; d+=32){
        float td = t[d];
        const float* w = wg + d*NE;
        #pragma unroll
        for(int e=0;e<NE;e++) acc[e] += td*w[e];
    }
    #pragma unroll
    for(int e=0;e<NE;e++)
        #pragma unroll
        for(int o=16;o>0;o>>=1) acc[e] += __shfl_xor_sync(0xffffffffu, acc[e], o);
    if(lane==0){
        float mx = -1e30f;
        #pragma unroll
        for(int e=0;e<NE;e++) mx = fmaxf(mx, acc[e]);
        float p[NE], s=0.f;
        #pragma unroll
        for(int e=0;e<NE;e++){ p[e] = expf(acc[e]-mx); s += p[e]; }
        float inv = 1.0f/s;
        #pragma unroll
        for(int e=0;e<NE;e++) p[e] *= inv;
        int e0 = 0;
        #pragma unroll
        for(int e=1;e<NE;e++) if(p[e] > p[e0]) e0 = e;
        int e1 = (e0==0) ? 1 : 0;
        #pragma unroll
        for(int e=0;e<NE;e++) if(e!=e0 && p[e] > p[e1]) e1 = e;
        float w0 = p[e0], w1 = p[e1];
        float rn = 1.0f/(w0+w1);
        w0 *= rn; w1 *= rn;
        int p0 = atomicAdd(&g_count[e0], 1);
        g_slot_token[e0*CAP + p0] = token; g_slot_w[e0*CAP + p0] = w0;
        int p1 = atomicAdd(&g_count[e1], 1);
        g_slot_token[e1*CAP + p1] = token; g_slot_w[e1*CAP + p1] = w1;
    }
}

// ================== launch ==================
extern "C" void kernel_launch(void* const* d_in, const int* in_sizes, int n_in,
                              void* d_out, int out_size)
{
    const float* x    = (const float*)d_in[0];
    const float* ln1w = (const float*)d_in[1];
    const float* ln1b = (const float*)d_in[2];
    const float* ln2w = (const float*)d_in[3];
    const float* ln2b = (const float*)d_in[4];
    const float* wqkv = (const float*)d_in[5];
    const float* bqkv = (const float*)d_in[6];
    const float* wo   = (const float*)d_in[7];
    const float* bo   = (const float*)d_in[8];
    const float* wg   = (const float*)d_in[9];
    const float* w1   = (const float*)d_in[10];
    const float* b1   = (const float*)d_in[11];
    const float* w2   = (const float*)d_in[12];
    const float* b2   = (const float*)d_in[13];
    float* out = (float*)d_out;

    float *p_ln, *p_qkv, *p_ctx;
    cudaGetSymbolAddress((void**)&p_ln,  g_ln);
    cudaGetSymbolAddress((void**)&p_qkv, g_qkv);
    cudaGetSymbolAddress((void**)&p_ctx, g_ctx);

    ln_kernel<<<NTOK, 256>>>(x, ln1w, ln1b, p_ln);
    tc_gemm_bias<<<dim3(3*ND/128, NTOK/128), 256>>>(p_ln, ND, wqkv, 3*ND, bqkv, nullptr, p_qkv, 3*ND, ND);
    tc_attn_scores<<<dim3(NT/128, NT/128, NB*NHEAD), 256>>>();
    softmax_kernel<<<(NB*NHEAD*NT)/8, 256>>>();
    tc_attn_ctx<<<dim3(1, NT/128, NB*NHEAD), 256>>>();
    tc_gemm_bias<<<dim3(ND/128, NTOK/128), 256>>>(p_ctx, ND, wo, ND, bo, x, out, ND, ND);
    ln_kernel<<<NTOK, 256>>>(out, ln2w, ln2b, p_ln);
    moe_reset_kernel<<<NSLOT/256, 256>>>();
    gate_kernel<<<NTOK/8, 256>>>(wg);
    tc_moe_gemm1<<<dim3(NF/128, NE*16), 256>>>(w1, b1);
    tc_moe_gemm2<<<dim3(ND/128, NE*16), 256>>>(w2, b2, out);
}

// round 9
// speedup vs baseline: 1.7415x; 1.2263x over previous
#include <cuda_runtime.h>
#include <cuda_fp16.h>
#include <math.h>

#define NB 4
#define NT 512
#define ND 1024
#define NF 4096
#define NE 8
#define NHEAD 16
#define DH 64
#define NTOK (NB*NT)          // 2048
#define CAP 2048
#define NSLOT (NE*CAP)

// ---- static scratch ----
__device__ float g_ln[NTOK*ND];
__device__ float g_qkv[(size_t)NTOK*3*ND];
__device__ float g_scores[(size_t)NB*NHEAD*NT*NT];
__device__ float g_ctx[(size_t)NTOK*ND];
__device__ float g_hidden[(size_t)NSLOT*NF];
__device__ int   g_slot_token[NSLOT];
__device__ float g_slot_w[NSLOT];
__device__ int   g_count[NE];

__device__ __forceinline__ float gelu_tanh(float x){
    float x3 = x*x*x;
    return 0.5f*x*(1.0f + tanhf(0.7978845608028654f*(x + 0.044715f*x3)));
}

// pack two fp32 -> fp16x2 (round-to-nearest)
__device__ __forceinline__ unsigned round_pack(float x0, float x1){
    return ((unsigned)__half_as_ushort(__float2half_rn(x1))<<16)
         |  (unsigned)__half_as_ushort(__float2half_rn(x0));
}

__device__ __forceinline__ void mma_f16(float* c, const unsigned* a, const unsigned* b){
    asm volatile("mma.sync.aligned.m16n8k16.row.col.f32.f16.f16.f32 "
        "{%0,%1,%2,%3}, {%4,%5,%6,%7}, {%8,%9}, {%0,%1,%2,%3};\n"
        : "+f"(c[0]),"+f"(c[1]),"+f"(c[2]),"+f"(c[3])
        : "r"(a[0]),"r"(a[1]),"r"(a[2]),"r"(a[3]), "r"(b[0]),"r"(b[1]));
}

// ================== pure-fp16 GEMM core ==================
// BM=128 fixed. Block = GM*GN warps (=8 -> 256 threads).
// A: fp32 row-major [M,K] (pre-offset to block row, or rmap gather), rounded fp16 in smem.
// B: fp32; if !BNK row-major [K,N] (pre-offset by n0); if BNK n-major [N,K] (pre-offset by n0 rows).
template<int BN,int GM,int GN,int WM,int WN,bool BNK>
__device__ __forceinline__ void core_f16(
    const float* __restrict__ A, int lda, const int* __restrict__ rmap,
    const float* __restrict__ Bm, int ldb, int K,
    float acc[WM][WN][4])
{
    constexpr int SA  = 24;               // A smem stride (fp16 elems)
    constexpr int SBk = BN + 8;           // B kn-layout stride
    constexpr int SBn = 24;               // B nk-layout stride
    constexpr int BSZ = BNK ? BN*SBn : 16*SBk;

    __shared__ __align__(16) __half As[128*SA];
    __shared__ __align__(16) __half Bs[BSZ];

    const int tid  = threadIdx.x;
    const int lane = tid & 31, w = tid >> 5;
    const int wm = (w % GM)*(WM*16);
    const int wn = (w / GM)*(WN*8);
    const int g = lane>>2, q = lane&3;

    // ---- A staging coords: row = tid>>1, k-offset = (tid&1)*8 ----
    const int ar = tid>>1, ak = (tid&1)*8;
    const float* Ap = nullptr;
    if(rmap){ int tok = rmap[ar]; if(tok>=0) Ap = A + (size_t)tok*lda + ak; }
    else      Ap = A + (size_t)ar*lda + ak;
    const int aoff = ar*SA + ak;

    // ---- B staging coords ----
    const float* Bp;
    int boff;
    if(BNK){
        const int bnr = tid>>1, bk = (tid&1)*8;
        Bp = Bm + (size_t)bnr*ldb + bk;
        boff = bnr*SBn + bk;
    } else if(BN==128){
        const int bkr = tid>>4, bn = (tid&15)*8;
        Bp = Bm + (size_t)bkr*ldb + bn;
        boff = bkr*SBk + bn;
    } else { // BN==64
        const int bkr = tid>>4, bn = (tid&15)*4;
        Bp = Bm + (size_t)bkr*ldb + bn;
        boff = bkr*SBk + bn;
    }

    for(int k0=0;k0<K;k0+=16){
        // ---- stage A (128x16) ----
        {
            float4 v0, v1;
            if(Ap){ v0 = *(const float4*)(Ap + k0); v1 = *(const float4*)(Ap + k0 + 4); }
            else  { v0 = make_float4(0,0,0,0); v1 = v0; }
            *(unsigned*)&As[aoff  ] = round_pack(v0.x,v0.y);
            *(unsigned*)&As[aoff+2] = round_pack(v0.z,v0.w);
            *(unsigned*)&As[aoff+4] = round_pack(v1.x,v1.y);
            *(unsigned*)&As[aoff+6] = round_pack(v1.z,v1.w);
        }
        // ---- stage B (16xBN or BNx16) ----
        {
            if(BNK){
                float4 u0 = *(const float4*)(Bp + k0);
                float4 u1 = *(const float4*)(Bp + k0 + 4);
                *(unsigned*)&Bs[boff  ] = round_pack(u0.x,u0.y);
                *(unsigned*)&Bs[boff+2] = round_pack(u0.z,u0.w);
                *(unsigned*)&Bs[boff+4] = round_pack(u1.x,u1.y);
                *(unsigned*)&Bs[boff+6] = round_pack(u1.z,u1.w);
            } else if(BN==128){
                float4 u0 = *(const float4*)(Bp + (size_t)k0*ldb);
                float4 u1 = *(const float4*)(Bp + (size_t)k0*ldb + 4);
                *(unsigned*)&Bs[boff  ] = round_pack(u0.x,u0.y);
                *(unsigned*)&Bs[boff+2] = round_pack(u0.z,u0.w);
                *(unsigned*)&Bs[boff+4] = round_pack(u1.x,u1.y);
                *(unsigned*)&Bs[boff+6] = round_pack(u1.z,u1.w);
            } else {
                float4 u0 = *(const float4*)(Bp + (size_t)k0*ldb);
                *(unsigned*)&Bs[boff  ] = round_pack(u0.x,u0.y);
                *(unsigned*)&Bs[boff+2] = round_pack(u0.z,u0.w);
            }
        }
        __syncthreads();

        // ---- fragments ----
        unsigned aR[WM][4], bR[WN][2];
        #pragma unroll
        for(int i=0;i<WM;i++){
            int r0 = (wm + i*16 + g    )*SA + q*2;
            int r1 = (wm + i*16 + g + 8)*SA + q*2;
            aR[i][0]=*(const unsigned*)&As[r0];   aR[i][1]=*(const unsigned*)&As[r1];
            aR[i][2]=*(const unsigned*)&As[r0+8]; aR[i][3]=*(const unsigned*)&As[r1+8];
        }
        #pragma unroll
        for(int j=0;j<WN;j++){
            int n = wn + j*8 + g;
            if(BNK){
                int o = n*SBn + q*2;
                bR[j][0]=*(const unsigned*)&Bs[o]; bR[j][1]=*(const unsigned*)&Bs[o+8];
            } else {
                const unsigned short* ph = (const unsigned short*)&Bs[(q*2)*SBk + n];
                bR[j][0] = (unsigned)ph[0]      | ((unsigned)ph[SBk]  <<16);
                bR[j][1] = (unsigned)ph[8*SBk]  | ((unsigned)ph[9*SBk]<<16);
            }
        }
        #pragma unroll
        for(int i=0;i<WM;i++)
            #pragma unroll
            for(int j=0;j<WN;j++)
                mma_f16(acc[i][j], aR[i], bR[j]);
        __syncthreads();
    }
}

// ================== GEMM kernels ==================

// C = A@B + bias (+res)
__global__ __launch_bounds__(256) void tc_gemm_bias(
    const float* __restrict__ A, int lda,
    const float* __restrict__ B, int ldb,
    const float* __restrict__ bias,
    const float* __restrict__ res,
    float* __restrict__ C, int ldc, int K)
{
    const int m0 = blockIdx.y*128, n0 = blockIdx.x*128;
    float acc[4][4][4] = {};
    core_f16<128,2,4,4,4,false>(A + (size_t)m0*lda, lda, nullptr, B + n0, ldb, K, acc);
    const int lane = threadIdx.x&31, w = threadIdx.x>>5;
    const int wm = (w&1)*64, wn = (w>>1)*32;
    const int g = lane>>2, q = lane&3;
    #pragma unroll
    for(int i=0;i<4;i++)
        #pragma unroll
        for(int j=0;j<4;j++)
            #pragma unroll
            for(int hh=0;hh<2;hh++){
                int row = m0 + wm + i*16 + g + hh*8;
                int col = n0 + wn + j*8 + q*2;
                float v0 = acc[i][j][hh*2]   + bias[col];
                float v1 = acc[i][j][hh*2+1] + bias[col+1];
                if(res){
                    float2 r = *(const float2*)&res[(size_t)row*ldc+col];
                    v0 += r.x; v1 += r.y;
                }
                float2 o; o.x=v0; o.y=v1;
                *(float2*)&C[(size_t)row*ldc+col] = o;
            }
}

// scores = Q @ K^T / 8  per (b,h)
__global__ __launch_bounds__(256) void tc_attn_scores()
{
    const int bh = blockIdx.z;
    const int b = bh>>4, h = bh&15;
    const float* Q  = g_qkv + (size_t)b*NT*3*ND + h*DH;
    const float* Kp = g_qkv + (size_t)b*NT*3*ND + ND + h*DH;
    float* S = g_scores + (size_t)bh*NT*NT;
    const int m0 = blockIdx.y*128, n0 = blockIdx.x*128;
    float acc[4][4][4] = {};
    core_f16<128,2,4,4,4,true>(Q + (size_t)m0*(3*ND), 3*ND, nullptr,
                               Kp + (size_t)n0*(3*ND), 3*ND, DH, acc);
    const int lane = threadIdx.x&31, w = threadIdx.x>>5;
    const int wm = (w&1)*64, wn = (w>>1)*32;
    const int g = lane>>2, q = lane&3;
    #pragma unroll
    for(int i=0;i<4;i++)
        #pragma unroll
        for(int j=0;j<4;j++)
            #pragma unroll
            for(int hh=0;hh<2;hh++){
                int row = m0 + wm + i*16 + g + hh*8;
                int col = n0 + wn + j*8 + q*2;
                float2 o;
                o.x = acc[i][j][hh*2]  *0.125f;
                o.y = acc[i][j][hh*2+1]*0.125f;
                *(float2*)&S[(size_t)row*NT+col] = o;
            }
}

// ctx = P @ V per (b,h): M=512, N=64, K=512
__global__ __launch_bounds__(256) void tc_attn_ctx()
{
    const int bh = blockIdx.z;
    const int b = bh>>4, h = bh&15;
    const float* P = g_scores + (size_t)bh*NT*NT;
    const float* V = g_qkv + (size_t)b*NT*3*ND + 2*ND + h*DH;
    const int m0 = blockIdx.y*128;
    float acc[2][4][4] = {};
    core_f16<64,4,2,2,4,false>(P + (size_t)m0*NT, NT, nullptr, V, 3*ND, NT, acc);
    const int lane = threadIdx.x&31, w = threadIdx.x>>5;
    const int wm = (w&3)*32, wn = (w>>2)*32;
    const int g = lane>>2, q = lane&3;
    #pragma unroll
    for(int i=0;i<2;i++)
        #pragma unroll
        for(int j=0;j<4;j++)
            #pragma unroll
            for(int hh=0;hh<2;hh++){
                int row = m0 + wm + i*16 + g + hh*8;
                int col = wn + j*8 + q*2;
                float2 o;
                o.x = acc[i][j][hh*2];
                o.y = acc[i][j][hh*2+1];
                *(float2*)&g_ctx[(size_t)(b*NT+row)*ND + h*DH + col] = o;
            }
}

// MoE GEMM1: hidden = gelu(gather(ln2) @ w1[e] + b1[e])
__global__ __launch_bounds__(256) void tc_moe_gemm1(
    const float* __restrict__ w1, const float* __restrict__ b1)
{
    const int e = blockIdx.y >> 4;
    const int rt = blockIdx.y & 15;
    const int cnt = g_count[e];
    if(rt*128 >= cnt) return;
    const int m0 = rt*128, n0 = blockIdx.x*128;
    float acc[4][4][4] = {};
    core_f16<128,2,4,4,4,false>(g_ln, ND, &g_slot_token[e*CAP + m0],
                                w1 + (size_t)e*ND*NF + n0, NF, ND, acc);
    const int lane = threadIdx.x&31, w = threadIdx.x>>5;
    const int wm = (w&1)*64, wn = (w>>1)*32;
    const int g = lane>>2, q = lane&3;
    #pragma unroll
    for(int i=0;i<4;i++)
        #pragma unroll
        for(int j=0;j<4;j++)
            #pragma unroll
            for(int hh=0;hh<2;hh++){
                int sl  = m0 + wm + i*16 + g + hh*8;
                int col = n0 + wn + j*8 + q*2;
                float v0 = gelu_tanh(acc[i][j][hh*2]   + b1[e*NF + col]);
                float v1 = gelu_tanh(acc[i][j][hh*2+1] + b1[e*NF + col+1]);
                float2 o; o.x=v0; o.y=v1;
                *(float2*)&g_hidden[(size_t)(e*CAP+sl)*NF + col] = o;
            }
}

// MoE GEMM2: out += w_slot * (hidden @ w2[e] + b2[e])
__global__ __launch_bounds__(256) void tc_moe_gemm2(
    const float* __restrict__ w2, const float* __restrict__ b2,
    float* __restrict__ out)
{
    const int e = blockIdx.y >> 4;
    const int rt = blockIdx.y & 15;
    const int cnt = g_count[e];
    if(rt*128 >= cnt) return;
    const int m0 = rt*128, n0 = blockIdx.x*128;
    float acc[4][4][4] = {};
    core_f16<128,2,4,4,4,false>(g_hidden + (size_t)(e*CAP + m0)*NF, NF, nullptr,
                                w2 + (size_t)e*NF*ND + n0, ND, NF, acc);
    const int lane = threadIdx.x&31, w = threadIdx.x>>5;
    const int wm = (w&1)*64, wn = (w>>1)*32;
    const int g = lane>>2, q = lane&3;
    #pragma unroll
    for(int i=0;i<4;i++)
        #pragma unroll
        for(int j=0;j<4;j++)
            #pragma unroll
            for(int hh=0;hh<2;hh++){
                int sl  = m0 + wm + i*16 + g + hh*8;
                if(sl < cnt){
                    int tok = g_slot_token[e*CAP + sl];
                    float ws = g_slot_w[e*CAP + sl];
                    int col = n0 + wn + j*8 + q*2;
                    atomicAdd(&out[(size_t)tok*ND + col],   ws*(acc[i][j][hh*2]   + b2[e*ND + col]));
                    atomicAdd(&out[(size_t)tok*ND + col+1], ws*(acc[i][j][hh*2+1] + b2[e*ND + col+1]));
                }
            }
}

// ================== non-GEMM kernels ==================

__global__ void ln_kernel(const float* __restrict__ x,
                          const float* __restrict__ w,
                          const float* __restrict__ b,
                          float* __restrict__ y)
{
    int row = blockIdx.x;
    int t = threadIdx.x;
    float4 v = *(const float4*)(x + (size_t)row*ND + t*4);
    float s = v.x+v.y+v.z+v.w;
    __shared__ float red[256];
    red[t] = s; __syncthreads();
    for(int o=128;o>0;o>>=1){ if(t<o) red[t]+=red[t+o]; __syncthreads(); }
    float mu = red[0]*(1.0f/ND);
    __syncthreads();
    float d0=v.x-mu, d1=v.y-mu, d2=v.z-mu, d3=v.w-mu;
    red[t] = d0*d0+d1*d1+d2*d2+d3*d3; __syncthreads();
    for(int o=128;o>0;o>>=1){ if(t<o) red[t]+=red[t+o]; __syncthreads(); }
    float rstd = rsqrtf(red[0]*(1.0f/ND) + 1e-5f);
    float4 wv = *(const float4*)(w + t*4);
    float4 bv = *(const float4*)(b + t*4);
    float4 o;
    o.x = d0*rstd*wv.x + bv.x;
    o.y = d1*rstd*wv.y + bv.y;
    o.z = d2*rstd*wv.z + bv.z;
    o.w = d3*rstd*wv.w + bv.w;
    *(float4*)(y + (size_t)row*ND + t*4) = o;
}

__global__ void softmax_kernel()
{
    int wrow = blockIdx.x*8 + (threadIdx.x>>5);
    int lane = threadIdx.x & 31;
    float* r = g_scores + (size_t)wrow*NT;
    float v[16];
    #pragma unroll
    for(int ii=0;ii<4;ii++)
        *(float4*)&v[ii*4] = *(const float4*)&r[lane*16 + ii*4];
    float mx = -1e30f;
    #pragma unroll
    for(int i=0;i<16;i++) mx = fmaxf(mx, v[i]);
    #pragma unroll
    for(int o=16;o>0;o>>=1) mx = fmaxf(mx, __shfl_xor_sync(0xffffffffu, mx, o));
    float s = 0.f;
    #pragma unroll
    for(int i=0;i<16;i++){ v[i] = expf(v[i]-mx); s += v[i]; }
    #pragma unroll
    for(int o=16;o>0;o>>=1) s += __shfl_xor_sync(0xffffffffu, s, o);
    float inv = 1.0f/s;
    #pragma unroll
    for(int ii=0;ii<4;ii++){
        float4 o;
        o.x = v[ii*4]*inv; o.y = v[ii*4+1]*inv; o.z = v[ii*4+2]*inv; o.w = v[ii*4+3]*inv;
        *(float4*)&r[lane*16 + ii*4] = o;
    }
}

__global__ void moe_reset_kernel()
{
    int i = blockIdx.x*256 + threadIdx.x;
    if(i < NSLOT) g_slot_token[i] = -1;
    if(i < NE) g_count[i] = 0;
}

__global__ void gate_kernel(const float* __restrict__ wg)
{
    int token = blockIdx.x*8 + (threadIdx.x>>5);
    int lane = threadIdx.x & 31;
    const float* t = g_ln + (size_t)token*ND;
    float acc[NE] = {};
    for(int d=lane; d<ND; d+=32){
        float td = t[d];
        const float* w = wg + d*NE;
        #pragma unroll
        for(int e=0;e<NE;e++) acc[e] += td*w[e];
    }
    #pragma unroll
    for(int e=0;e<NE;e++)
        #pragma unroll
        for(int o=16;o>0;o>>=1) acc[e] += __shfl_xor_sync(0xffffffffu, acc[e], o);
    if(lane==0){
        float mx = -1e30f;
        #pragma unroll
        for(int e=0;e<NE;e++) mx = fmaxf(mx, acc[e]);
        float p[NE], s=0.f;
        #pragma unroll
        for(int e=0;e<NE;e++){ p[e] = expf(acc[e]-mx); s += p[e]; }
        float inv = 1.0f/s;
        #pragma unroll
        for(int e=0;e<NE;e++) p[e] *= inv;
        int e0 = 0;
        #pragma unroll
        for(int e=1;e<NE;e++) if(p[e] > p[e0]) e0 = e;
        int e1 = (e0==0) ? 1 : 0;
        #pragma unroll
        for(int e=0;e<NE;e++) if(e!=e0 && p[e] > p[e1]) e1 = e;
        float w0 = p[e0], w1 = p[e1];
        float rn = 1.0f/(w0+w1);
        w0 *= rn; w1 *= rn;
        int p0 = atomicAdd(&g_count[e0], 1);
        g_slot_token[e0*CAP + p0] = token; g_slot_w[e0*CAP + p0] = w0;
        int p1 = atomicAdd(&g_count[e1], 1);
        g_slot_token[e1*CAP + p1] = token; g_slot_w[e1*CAP + p1] = w1;
    }
}

// ================== launch ==================
extern "C" void kernel_launch(void* const* d_in, const int* in_sizes, int n_in,
                              void* d_out, int out_size)
{
    const float* x    = (const float*)d_in[0];
    const float* ln1w = (const float*)d_in[1];
    const float* ln1b = (const float*)d_in[2];
    const float* ln2w = (const float*)d_in[3];
    const float* ln2b = (const float*)d_in[4];
    const float* wqkv = (const float*)d_in[5];
    const float* bqkv = (const float*)d_in[6];
    const float* wo   = (const float*)d_in[7];
    const float* bo   = (const float*)d_in[8];
    const float* wg   = (const float*)d_in[9];
    const float* w1   = (const float*)d_in[10];
    const float* b1   = (const float*)d_in[11];
    const float* w2   = (const float*)d_in[12];
    const float* b2   = (const float*)d_in[13];
    float* out = (float*)d_out;

    float *p_ln, *p_qkv, *p_ctx;
    cudaGetSymbolAddress((void**)&p_ln,  g_ln);
    cudaGetSymbolAddress((void**)&p_qkv, g_qkv);
    cudaGetSymbolAddress((void**)&p_ctx, g_ctx);

    ln_kernel<<<NTOK, 256>>>(x, ln1w, ln1b, p_ln);
    tc_gemm_bias<<<dim3(3*ND/128, NTOK/128), 256>>>(p_ln, ND, wqkv, 3*ND, bqkv, nullptr, p_qkv, 3*ND, ND);
    tc_attn_scores<<<dim3(NT/128, NT/128, NB*NHEAD), 256>>>();
    softmax_kernel<<<(NB*NHEAD*NT)/8, 256>>>();
    tc_attn_ctx<<<dim3(1, NT/128, NB*NHEAD), 256>>>();
    tc_gemm_bias<<<dim3(ND/128, NTOK/128), 256>>>(p_ctx, ND, wo, ND, bo, x, out, ND, ND);
    ln_kernel<<<NTOK, 256>>>(out, ln2w, ln2b, p_ln);
    moe_reset_kernel<<<NSLOT/256, 256>>>();
    gate_kernel<<<NTOK/8, 256>>>(wg);
    tc_moe_gemm1<<<dim3(NF/128, NE*16), 256>>>(w1, b1);
    tc_moe_gemm2<<<dim3(ND/128, NE*16), 256>>>(w2, b2, out);
}

// round 10
// speedup vs baseline: 2.7207x; 1.5622x over previous
#include <cuda_runtime.h>
#include <cuda_fp16.h>
#include <math.h>

#define NB 4
#define NT 512
#define ND 1024
#define NF 4096
#define NE 8
#define NHEAD 16
#define DH 64
#define NTOK (NB*NT)          // 2048
#define CAP 2048
#define NSLOT (NE*CAP)
typedef __half h16;

// ---- static scratch ----
__device__ float g_ln[NTOK*ND];                          // fp32 ln (gate input)
__device__ float g_scores[(size_t)NB*NHEAD*NT*NT];       // fp32 scores (softmax input)
__device__ h16 g_lnh[NTOK*ND];
__device__ h16 g_qkvh[(size_t)NTOK*3*ND];
__device__ h16 g_Ph[(size_t)NB*NHEAD*NT*NT];
__device__ h16 g_ctxh[NTOK*ND];
__device__ h16 g_hidh[(size_t)NSLOT*NF];
__device__ h16 g_wqkvh[3*ND*ND];
__device__ h16 g_woh[ND*ND];
__device__ h16 g_w1h[(size_t)NE*ND*NF];
__device__ h16 g_w2h[(size_t)NE*NF*ND];
__device__ int   g_slot_token[NSLOT];
__device__ float g_slot_w[NSLOT];
__device__ int   g_count[NE];

__device__ __forceinline__ float gelu_tanh(float x){
    float x3 = x*x*x;
    return 0.5f*x*(1.0f + tanhf(0.7978845608028654f*(x + 0.044715f*x3)));
}
__device__ __forceinline__ unsigned round_pack(float x0, float x1){
    return ((unsigned)__half_as_ushort(__float2half_rn(x1))<<16)
         |  (unsigned)__half_as_ushort(__float2half_rn(x0));
}
__device__ __forceinline__ unsigned sptr(const void* p){
    return (unsigned)__cvta_generic_to_shared(p);
}
#define CPA16(dst,src)    asm volatile("cp.async.cg.shared.global [%0],[%1],16;\n"::"r"(dst),"l"(src):"memory")
#define CPA16Z(dst,src,z) asm volatile("cp.async.cg.shared.global [%0],[%1],16,%2;\n"::"r"(dst),"l"(src),"r"(z):"memory")
#define CPCOMMIT          asm volatile("cp.async.commit_group;\n":::"memory")
__device__ __forceinline__ void cp_wait0(){ asm volatile("cp.async.wait_group 0;\n":::"memory"); }
__device__ __forceinline__ void cp_wait1(){ asm volatile("cp.async.wait_group 1;\n":::"memory"); }

__device__ __forceinline__ void mma_f16(float* c, const unsigned* a, const unsigned* b){
    asm volatile("mma.sync.aligned.m16n8k16.row.col.f32.f16.f16.f32 "
        "{%0,%1,%2,%3}, {%4,%5,%6,%7}, {%8,%9}, {%0,%1,%2,%3};\n"
        : "+f"(c[0]),"+f"(c[1]),"+f"(c[2]),"+f"(c[3])
        : "r"(a[0]),"r"(a[1]),"r"(a[2]),"r"(a[3]), "r"(b[0]),"r"(b[1]));
}

// ================== fp16 GEMM core, cp.async double-buffered, BK=32 ==================
// BM=128 fixed. 256 threads = GM*GN warps; warp tile (WM*16)x(WN*8).
// A: fp16 row-major [M,K] (pre-offset to block row, or rmap gather).
// B: fp16; if !BNK k-major [K,N] (pre-offset by n0); if BNK n-major [N,K] (pre-offset by n0 rows).
template<int BN,int GM,int GN,int WM,int WN,bool BNK>
__device__ __forceinline__ void core_h(
    const h16* __restrict__ A, int lda, const int* __restrict__ rmap,
    const h16* __restrict__ Bm, int ldb, int K,
    float acc[WM][WN][4])
{
    constexpr int SA  = 40;                 // halves per A smem row (32 + 8 pad)
    constexpr int SBk = BN + 8;             // B kn stride
    constexpr int SBn = 40;                 // B nk stride
    constexpr int BSZ = BNK ? 128*SBn : 32*SBk;

    __shared__ __align__(16) h16 As[2][128*SA];
    __shared__ __align__(16) h16 Bs[2][BSZ];

    const int tid=threadIdx.x, lane=tid&31, w=tid>>5;
    const int wm=(w%GM)*(WM*16), wn=(w/GM)*(WN*8);
    const int g=lane>>2, q=lane&3;

    // A staging: row = tid>>1, two 16B chunks at half-offsets (tid&1)*16, +8
    const int ar = tid>>1, ak = (tid&1)*16;
    const h16* Ap;
    unsigned az = 16;
    if(rmap){ int tok=rmap[ar]; if(tok<0){ az=0; tok=0; } Ap = A + (size_t)tok*lda + ak; }
    else      Ap = A + (size_t)ar*lda + ak;
    const unsigned aoff = ar*SA + ak;

    // B staging coords
    const h16* Bp; unsigned boff;
    if(BNK){
        const int br = tid>>1, bk = (tid&1)*16;
        Bp = Bm + (size_t)br*ldb + bk; boff = br*SBn + bk;
    } else if(BN==128){
        const int br = tid>>3, bc = (tid&7)*16;
        Bp = Bm + (size_t)br*ldb + bc; boff = br*SBk + bc;
    } else { // BN==64: 32x64 halves = 256 16B chunks, 1/thread
        const int br = tid>>3, bc = (tid&7)*8;
        Bp = Bm + (size_t)br*ldb + bc; boff = br*SBk + bc;
    }

    auto stage = [&](int s, int k0){
        if(rmap){
            CPA16Z(sptr(&As[s][aoff]),   Ap + k0,     az);
            CPA16Z(sptr(&As[s][aoff+8]), Ap + k0 + 8, az);
        } else {
            CPA16(sptr(&As[s][aoff]),   Ap + k0);
            CPA16(sptr(&As[s][aoff+8]), Ap + k0 + 8);
        }
        if(BNK){
            CPA16(sptr(&Bs[s][boff]),   Bp + k0);
            CPA16(sptr(&Bs[s][boff+8]), Bp + k0 + 8);
        } else if(BN==128){
            CPA16(sptr(&Bs[s][boff]),   Bp + (size_t)k0*ldb);
            CPA16(sptr(&Bs[s][boff+8]), Bp + (size_t)k0*ldb + 8);
        } else {
            CPA16(sptr(&Bs[s][boff]),   Bp + (size_t)k0*ldb);
        }
    };

    auto compute = [&](int s){
        #pragma unroll
        for(int kk=0;kk<32;kk+=16){
            unsigned aR[WM][4], bR[WN][2];
            #pragma unroll
            for(int i=0;i<WM;i++){
                int r0 = (wm + i*16 + g)*SA + kk + q*2;
                int r1 = r0 + 8*SA;
                aR[i][0]=*(const unsigned*)&As[s][r0];   aR[i][1]=*(const unsigned*)&As[s][r1];
                aR[i][2]=*(const unsigned*)&As[s][r0+8]; aR[i][3]=*(const unsigned*)&As[s][r1+8];
            }
            #pragma unroll
            for(int j=0;j<WN;j++){
                int n = wn + j*8 + g;
                if(BNK){
                    int o = n*SBn + kk + q*2;
                    bR[j][0]=*(const unsigned*)&Bs[s][o]; bR[j][1]=*(const unsigned*)&Bs[s][o+8];
                } else {
                    const unsigned short* ph = (const unsigned short*)&Bs[s][(kk+q*2)*SBk + n];
                    bR[j][0] = (unsigned)ph[0]      | ((unsigned)ph[SBk]  <<16);
                    bR[j][1] = (unsigned)ph[8*SBk]  | ((unsigned)ph[9*SBk]<<16);
                }
            }
            #pragma unroll
            for(int i=0;i<WM;i++)
                #pragma unroll
                for(int j=0;j<WN;j++)
                    mma_f16(acc[i][j], aR[i], bR[j]);
        }
    };

    const int KT = K/32;
    stage(0, 0); CPCOMMIT;
    for(int s2=0;s2<KT;s2++){
        const int buf = s2&1;
        if(s2+1<KT){ stage(buf^1, (s2+1)*32); CPCOMMIT; cp_wait1(); }
        else cp_wait0();
        __syncthreads();
        compute(buf);
        __syncthreads();
    }
}

// ================== GEMM kernels ==================

// qkv = ln1h @ wqkvh + bias -> fp16
__global__ __launch_bounds__(256,2) void tc_qkv(const float* __restrict__ bias){
    const int m0 = blockIdx.y*128, n0 = blockIdx.x*128;
    float acc[4][4][4] = {};
    core_h<128,2,4,4,4,false>(g_lnh + (size_t)m0*ND, ND, nullptr, g_wqkvh + n0, 3*ND, ND, acc);
    const int lane = threadIdx.x&31, w = threadIdx.x>>5;
    const int wm = (w&1)*64, wn = (w>>1)*32;
    const int g = lane>>2, q = lane&3;
    #pragma unroll
    for(int i=0;i<4;i++)
        #pragma unroll
        for(int j=0;j<4;j++)
            #pragma unroll
            for(int hh=0;hh<2;hh++){
                int row = m0 + wm + i*16 + g + hh*8;
                int col = n0 + wn + j*8 + q*2;
                *(unsigned*)&g_qkvh[(size_t)row*3*ND+col] =
                    round_pack(acc[i][j][hh*2] + bias[col], acc[i][j][hh*2+1] + bias[col+1]);
            }
}

// scores = Q @ K^T / 8 -> fp32
__global__ __launch_bounds__(256,2) void tc_attn_scores(){
    const int bh = blockIdx.z, b = bh>>4, h = bh&15;
    const int m0 = blockIdx.y*128, n0 = blockIdx.x*128;
    const size_t qb = (size_t)b*NT*3*ND;
    float acc[4][4][4] = {};
    core_h<128,2,4,4,4,true>(g_qkvh + qb + (size_t)m0*3*ND + h*DH, 3*ND, nullptr,
                             g_qkvh + qb + ND + h*DH + (size_t)n0*3*ND, 3*ND, DH, acc);
    float* S = g_scores + (size_t)bh*NT*NT;
    const int lane = threadIdx.x&31, w = threadIdx.x>>5;
    const int wm = (w&1)*64, wn = (w>>1)*32;
    const int g = lane>>2, q = lane&3;
    #pragma unroll
    for(int i=0;i<4;i++)
        #pragma unroll
        for(int j=0;j<4;j++)
            #pragma unroll
            for(int hh=0;hh<2;hh++){
                int row = m0 + wm + i*16 + g + hh*8;
                int col = n0 + wn + j*8 + q*2;
                float2 o;
                o.x = acc[i][j][hh*2]  *0.125f;
                o.y = acc[i][j][hh*2+1]*0.125f;
                *(float2*)&S[(size_t)row*NT+col] = o;
            }
}

// ctx = P @ V -> fp16
__global__ __launch_bounds__(256,2) void tc_attn_ctx(){
    const int bh = blockIdx.z, b = bh>>4, h = bh&15;
    const int m0 = blockIdx.y*128;
    const size_t qb = (size_t)b*NT*3*ND;
    float acc[2][4][4] = {};
    core_h<64,4,2,2,4,false>(g_Ph + (size_t)bh*NT*NT + (size_t)m0*NT, NT, nullptr,
                             g_qkvh + qb + 2*ND + h*DH, 3*ND, NT, acc);
    const int lane = threadIdx.x&31, w = threadIdx.x>>5;
    const int wm = (w&3)*32, wn = (w>>2)*32;
    const int g = lane>>2, q = lane&3;
    #pragma unroll
    for(int i=0;i<2;i++)
        #pragma unroll
        for(int j=0;j<4;j++)
            #pragma unroll
            for(int hh=0;hh<2;hh++){
                int row = m0 + wm + i*16 + g + hh*8;
                int col = wn + j*8 + q*2;
                *(unsigned*)&g_ctxh[(size_t)(b*NT+row)*ND + h*DH + col] =
                    round_pack(acc[i][j][hh*2], acc[i][j][hh*2+1]);
            }
}

// out = ctx @ wo + bias + residual -> fp32
__global__ __launch_bounds__(256,2) void tc_o(
    const float* __restrict__ bias, const float* __restrict__ res, float* __restrict__ out){
    const int m0 = blockIdx.y*128, n0 = blockIdx.x*128;
    float acc[4][4][4] = {};
    core_h<128,2,4,4,4,false>(g_ctxh + (size_t)m0*ND, ND, nullptr, g_woh + n0, ND, ND, acc);
    const int lane = threadIdx.x&31, w = threadIdx.x>>5;
    const int wm = (w&1)*64, wn = (w>>1)*32;
    const int g = lane>>2, q = lane&3;
    #pragma unroll
    for(int i=0;i<4;i++)
        #pragma unroll
        for(int j=0;j<4;j++)
            #pragma unroll
            for(int hh=0;hh<2;hh++){
                int row = m0 + wm + i*16 + g + hh*8;
                int col = n0 + wn + j*8 + q*2;
                float2 r = *(const float2*)&res[(size_t)row*ND+col];
                float2 o;
                o.x = acc[i][j][hh*2]   + bias[col]   + r.x;
                o.y = acc[i][j][hh*2+1] + bias[col+1] + r.y;
                *(float2*)&out[(size_t)row*ND+col] = o;
            }
}

// MoE GEMM1 -> fp16 hidden
__global__ __launch_bounds__(256,2) void tc_moe_gemm1(const float* __restrict__ b1){
    const int e = blockIdx.y >> 4;
    const int rt = blockIdx.y & 15;
    if(rt*128 >= g_count[e]) return;
    const int m0 = rt*128, n0 = blockIdx.x*128;
    float acc[4][4][4] = {};
    core_h<128,2,4,4,4,false>(g_lnh, ND, &g_slot_token[e*CAP + m0],
                              g_w1h + (size_t)e*ND*NF + n0, NF, ND, acc);
    const int lane = threadIdx.x&31, w = threadIdx.x>>5;
    const int wm = (w&1)*64, wn = (w>>1)*32;
    const int g = lane>>2, q = lane&3;
    #pragma unroll
    for(int i=0;i<4;i++)
        #pragma unroll
        for(int j=0;j<4;j++)
            #pragma unroll
            for(int hh=0;hh<2;hh++){
                int sl  = m0 + wm + i*16 + g + hh*8;
                int col = n0 + wn + j*8 + q*2;
                float v0 = gelu_tanh(acc[i][j][hh*2]   + b1[e*NF + col]);
                float v1 = gelu_tanh(acc[i][j][hh*2+1] + b1[e*NF + col+1]);
                *(unsigned*)&g_hidh[(size_t)(e*CAP+sl)*NF + col] = round_pack(v0, v1);
            }
}

// MoE GEMM2: out += w_slot * (hidden @ w2 + b2)
__global__ __launch_bounds__(256,2) void tc_moe_gemm2(const float* __restrict__ b2, float* __restrict__ out){
    const int e = blockIdx.y >> 4;
    const int rt = blockIdx.y & 15;
    const int cnt = g_count[e];
    if(rt*128 >= cnt) return;
    const int m0 = rt*128, n0 = blockIdx.x*128;
    float acc[4][4][4] = {};
    core_h<128,2,4,4,4,false>(g_hidh + (size_t)(e*CAP + m0)*NF, NF, nullptr,
                              g_w2h + (size_t)e*NF*ND + n0, ND, NF, acc);
    const int lane = threadIdx.x&31, w = threadIdx.x>>5;
    const int wm = (w&1)*64, wn = (w>>1)*32;
    const int g = lane>>2, q = lane&3;
    #pragma unroll
    for(int i=0;i<4;i++)
        #pragma unroll
        for(int j=0;j<4;j++)
            #pragma unroll
            for(int hh=0;hh<2;hh++){
                int sl = m0 + wm + i*16 + g + hh*8;
                if(sl < cnt){
                    int tok = g_slot_token[e*CAP + sl];
                    float ws = g_slot_w[e*CAP + sl];
                    int col = n0 + wn + j*8 + q*2;
                    atomicAdd(&out[(size_t)tok*ND + col],   ws*(acc[i][j][hh*2]   + b2[e*ND + col]));
                    atomicAdd(&out[(size_t)tok*ND + col+1], ws*(acc[i][j][hh*2+1] + b2[e*ND + col+1]));
                }
            }
}

// ================== auxiliary kernels ==================

// fp32 -> fp16, 8 elems/thread
__global__ void conv_h_kernel(const float* __restrict__ src, h16* __restrict__ dst){
    size_t i = ((size_t)blockIdx.x*256 + threadIdx.x)*8;
    float4 a = *(const float4*)(src + i);
    float4 b = *(const float4*)(src + i + 4);
    *(uint4*)&dst[i] = make_uint4(round_pack(a.x,a.y), round_pack(a.z,a.w),
                                  round_pack(b.x,b.y), round_pack(b.z,b.w));
}

__global__ void ln_kernel(const float* __restrict__ x,
                          const float* __restrict__ w,
                          const float* __restrict__ b,
                          float* __restrict__ y, h16* __restrict__ yh)
{
    int row = blockIdx.x;
    int t = threadIdx.x;
    float4 v = *(const float4*)(x + (size_t)row*ND + t*4);
    float s = v.x+v.y+v.z+v.w;
    __shared__ float red[256];
    red[t] = s; __syncthreads();
    for(int o=128;o>0;o>>=1){ if(t<o) red[t]+=red[t+o]; __syncthreads(); }
    float mu = red[0]*(1.0f/ND);
    __syncthreads();
    float d0=v.x-mu, d1=v.y-mu, d2=v.z-mu, d3=v.w-mu;
    red[t] = d0*d0+d1*d1+d2*d2+d3*d3; __syncthreads();
    for(int o=128;o>0;o>>=1){ if(t<o) red[t]+=red[t+o]; __syncthreads(); }
    float rstd = rsqrtf(red[0]*(1.0f/ND) + 1e-5f);
    float4 wv = *(const float4*)(w + t*4);
    float4 bv = *(const float4*)(b + t*4);
    float4 o;
    o.x = d0*rstd*wv.x + bv.x;
    o.y = d1*rstd*wv.y + bv.y;
    o.z = d2*rstd*wv.z + bv.z;
    o.w = d3*rstd*wv.w + bv.w;
    *(float4*)(y + (size_t)row*ND + t*4) = o;
    *(uint2*)&yh[(size_t)row*ND + t*4] = make_uint2(round_pack(o.x,o.y), round_pack(o.z,o.w));
}

__global__ void softmax_kernel()
{
    int wrow = blockIdx.x*8 + (threadIdx.x>>5);
    int lane = threadIdx.x & 31;
    const float* r = g_scores + (size_t)wrow*NT;
    float v[16];
    #pragma unroll
    for(int ii=0;ii<4;ii++)
        *(float4*)&v[ii*4] = *(const float4*)&r[lane*16 + ii*4];
    float mx = -1e30f;
    #pragma unroll
    for(int i=0;i<16;i++) mx = fmaxf(mx, v[i]);
    #pragma unroll
    for(int o=16;o>0;o>>=1) mx = fmaxf(mx, __shfl_xor_sync(0xffffffffu, mx, o));
    float s = 0.f;
    #pragma unroll
    for(int i=0;i<16;i++){ v[i] = expf(v[i]-mx); s += v[i]; }
    #pragma unroll
    for(int o=16;o>0;o>>=1) s += __shfl_xor_sync(0xffffffffu, s, o);
    float inv = 1.0f/s;
    size_t base = (size_t)wrow*NT + lane*16;
    #pragma unroll
    for(int ii=0;ii<2;ii++){
        uint4 pk;
        pk.x = round_pack(v[ii*8  ]*inv, v[ii*8+1]*inv);
        pk.y = round_pack(v[ii*8+2]*inv, v[ii*8+3]*inv);
        pk.z = round_pack(v[ii*8+4]*inv, v[ii*8+5]*inv);
        pk.w = round_pack(v[ii*8+6]*inv, v[ii*8+7]*inv);
        *(uint4*)&g_Ph[base + ii*8] = pk;
    }
}

__global__ void moe_reset_kernel()
{
    int i = blockIdx.x*256 + threadIdx.x;
    if(i < NSLOT) g_slot_token[i] = -1;
    if(i < NE) g_count[i] = 0;
}

__global__ void gate_kernel(const float* __restrict__ wg)
{
    int token = blockIdx.x*8 + (threadIdx.x>>5);
    int lane = threadIdx.x & 31;
    const float* t = g_ln + (size_t)token*ND;
    float acc[NE] = {};
    for(int d=lane; d<ND; d+=32){
        float td = t[d];
        const float* w = wg + d*NE;
        #pragma unroll
        for(int e=0;e<NE;e++) acc[e] += td*w[e];
    }
    #pragma unroll
    for(int e=0;e<NE;e++)
        #pragma unroll
        for(int o=16;o>0;o>>=1) acc[e] += __shfl_xor_sync(0xffffffffu, acc[e], o);
    if(lane==0){
        float mx = -1e30f;
        #pragma unroll
        for(int e=0;e<NE;e++) mx = fmaxf(mx, acc[e]);
        float p[NE], s=0.f;
        #pragma unroll
        for(int e=0;e<NE;e++){ p[e] = expf(acc[e]-mx); s += p[e]; }
        float inv = 1.0f/s;
        #pragma unroll
        for(int e=0;e<NE;e++) p[e] *= inv;
        int e0 = 0;
        #pragma unroll
        for(int e=1;e<NE;e++) if(p[e] > p[e0]) e0 = e;
        int e1 = (e0==0) ? 1 : 0;
        #pragma unroll
        for(int e=0;e<NE;e++) if(e!=e0 && p[e] > p[e1]) e1 = e;
        float w0 = p[e0], w1 = p[e1];
        float rn = 1.0f/(w0+w1);
        w0 *= rn; w1 *= rn;
        int p0 = atomicAdd(&g_count[e0], 1);
        g_slot_token[e0*CAP + p0] = token; g_slot_w[e0*CAP + p0] = w0;
        int p1 = atomicAdd(&g_count[e1], 1);
        g_slot_token[e1*CAP + p1] = token; g_slot_w[e1*CAP + p1] = w1;
    }
}

// ================== launch ==================
extern "C" void kernel_launch(void* const* d_in, const int* in_sizes, int n_in,
                              void* d_out, int out_size)
{
    const float* x    = (const float*)d_in[0];
    const float* ln1w = (const float*)d_in[1];
    const float* ln1b = (const float*)d_in[2];
    const float* ln2w = (const float*)d_in[3];
    const float* ln2b = (const float*)d_in[4];
    const float* wqkv = (const float*)d_in[5];
    const float* bqkv = (const float*)d_in[6];
    const float* wo   = (const float*)d_in[7];
    const float* bo   = (const float*)d_in[8];
    const float* wg   = (const float*)d_in[9];
    const float* w1   = (const float*)d_in[10];
    const float* b1   = (const float*)d_in[11];
    const float* w2   = (const float*)d_in[12];
    const float* b2   = (const float*)d_in[13];
    float* out = (float*)d_out;

    float *p_ln;
    h16 *p_lnh, *p_wqkvh, *p_woh, *p_w1h, *p_w2h;
    cudaGetSymbolAddress((void**)&p_ln,    g_ln);
    cudaGetSymbolAddress((void**)&p_lnh,   g_lnh);
    cudaGetSymbolAddress((void**)&p_wqkvh, g_wqkvh);
    cudaGetSymbolAddress((void**)&p_woh,   g_woh);
    cudaGetSymbolAddress((void**)&p_w1h,   g_w1h);
    cudaGetSymbolAddress((void**)&p_w2h,   g_w2h);

    // weight fp32->fp16 (once per call)
    conv_h_kernel<<<3*ND*ND/2048, 256>>>(wqkv, p_wqkvh);
    conv_h_kernel<<<ND*ND/2048,   256>>>(wo,   p_woh);
    conv_h_kernel<<<NE*ND*NF/2048,256>>>(w1,   p_w1h);
    conv_h_kernel<<<NE*NF*ND/2048,256>>>(w2,   p_w2h);

    ln_kernel<<<NTOK, 256>>>(x, ln1w, ln1b, p_ln, p_lnh);
    tc_qkv<<<dim3(3*ND/128, NTOK/128), 256>>>(bqkv);
    tc_attn_scores<<<dim3(NT/128, NT/128, NB*NHEAD), 256>>>();
    softmax_kernel<<<(NB*NHEAD*NT)/8, 256>>>();
    tc_attn_ctx<<<dim3(1, NT/128, NB*NHEAD), 256>>>();
    tc_o<<<dim3(ND/128, NTOK/128), 256>>>(bo, x, out);
    ln_kernel<<<NTOK, 256>>>(out, ln2w, ln2b, p_ln, p_lnh);
    moe_reset_kernel<<<NSLOT/256, 256>>>();
    gate_kernel<<<NTOK/8, 256>>>(wg);
    tc_moe_gemm1<<<dim3(NF/128, NE*16), 256>>>(b1);
    tc_moe_gemm2<<<dim3(ND/128, NE*16), 256>>>(b2, out);
}

// round 11
// speedup vs baseline: 2.8258x; 1.0386x over previous
#include <cuda_runtime.h>
#include <cuda_fp16.h>
#include <math.h>

#define NB 4
#define NT 512
#define ND 1024
#define NF 4096
#define NE 8
#define NHEAD 16
#define DH 64
#define NTOK (NB*NT)          // 2048
#define CAP 2048
#define NSLOT (NE*CAP)
typedef __half h16;

// ---- static scratch ----
__device__ float g_ln[NTOK*ND];                          // fp32 ln (gate input)
__device__ h16 g_lnh[NTOK*ND];
__device__ h16 g_qkvh[(size_t)NTOK*3*ND];
__device__ h16 g_ctxh[NTOK*ND];
__device__ h16 g_hidh[(size_t)NSLOT*NF];
__device__ h16 g_wqkvh[3*ND*ND];
__device__ h16 g_woh[ND*ND];
__device__ h16 g_w1h[(size_t)NE*ND*NF];
__device__ h16 g_w2h[(size_t)NE*NF*ND];
__device__ int   g_slot_token[NSLOT];
__device__ float g_slot_w[NSLOT];
__device__ int   g_count[NE];

__device__ __forceinline__ float gelu_tanh(float x){
    float x3 = x*x*x;
    return 0.5f*x*(1.0f + tanhf(0.7978845608028654f*(x + 0.044715f*x3)));
}
__device__ __forceinline__ unsigned round_pack(float x0, float x1){
    return ((unsigned)__half_as_ushort(__float2half_rn(x1))<<16)
         |  (unsigned)__half_as_ushort(__float2half_rn(x0));
}
__device__ __forceinline__ unsigned sptr(const void* p){
    return (unsigned)__cvta_generic_to_shared(p);
}
#define CPA16(dst,src)    asm volatile("cp.async.cg.shared.global [%0],[%1],16;\n"::"r"(dst),"l"(src):"memory")
#define CPA16Z(dst,src,z) asm volatile("cp.async.cg.shared.global [%0],[%1],16,%2;\n"::"r"(dst),"l"(src),"r"(z):"memory")
#define CPCOMMIT          asm volatile("cp.async.commit_group;\n":::"memory")
__device__ __forceinline__ void cp_wait0(){ asm volatile("cp.async.wait_group 0;\n":::"memory"); }
__device__ __forceinline__ void cp_wait1(){ asm volatile("cp.async.wait_group 1;\n":::"memory"); }

__device__ __forceinline__ void mma_f16(float* c, const unsigned* a, const unsigned* b){
    asm volatile("mma.sync.aligned.m16n8k16.row.col.f32.f16.f16.f32 "
        "{%0,%1,%2,%3}, {%4,%5,%6,%7}, {%8,%9}, {%0,%1,%2,%3};\n"
        : "+f"(c[0]),"+f"(c[1]),"+f"(c[2]),"+f"(c[3])
        : "r"(a[0]),"r"(a[1]),"r"(a[2]),"r"(a[3]), "r"(b[0]),"r"(b[1]));
}

// ================== fp16 GEMM core, cp.async double-buffered, BK=32 ==================
template<int BN,int GM,int GN,int WM,int WN,bool BNK>
__device__ __forceinline__ void core_h(
    const h16* __restrict__ A, int lda, const int* __restrict__ rmap,
    const h16* __restrict__ Bm, int ldb, int K,
    float acc[WM][WN][4])
{
    constexpr int SA  = 40;
    constexpr int SBk = BN + 8;
    constexpr int SBn = 40;
    constexpr int BSZ = BNK ? 128*SBn : 32*SBk;

    __shared__ __align__(16) h16 As[2][128*SA];
    __shared__ __align__(16) h16 Bs[2][BSZ];

    const int tid=threadIdx.x, lane=tid&31, w=tid>>5;
    const int wm=(w%GM)*(WM*16), wn=(w/GM)*(WN*8);
    const int g=lane>>2, q=lane&3;

    const int ar = tid>>1, ak = (tid&1)*16;
    const h16* Ap;
    unsigned az = 16;
    if(rmap){ int tok=rmap[ar]; if(tok<0){ az=0; tok=0; } Ap = A + (size_t)tok*lda + ak; }
    else      Ap = A + (size_t)ar*lda + ak;
    const unsigned aoff = ar*SA + ak;

    const h16* Bp; unsigned boff;
    if(BNK){
        const int br = tid>>1, bk = (tid&1)*16;
        Bp = Bm + (size_t)br*ldb + bk; boff = br*SBn + bk;
    } else if(BN==128){
        const int br = tid>>3, bc = (tid&7)*16;
        Bp = Bm + (size_t)br*ldb + bc; boff = br*SBk + bc;
    } else {
        const int br = tid>>3, bc = (tid&7)*8;
        Bp = Bm + (size_t)br*ldb + bc; boff = br*SBk + bc;
    }

    auto stage = [&](int s, int k0){
        if(rmap){
            CPA16Z(sptr(&As[s][aoff]),   Ap + k0,     az);
            CPA16Z(sptr(&As[s][aoff+8]), Ap + k0 + 8, az);
        } else {
            CPA16(sptr(&As[s][aoff]),   Ap + k0);
            CPA16(sptr(&As[s][aoff+8]), Ap + k0 + 8);
        }
        if(BNK){
            CPA16(sptr(&Bs[s][boff]),   Bp + k0);
            CPA16(sptr(&Bs[s][boff+8]), Bp + k0 + 8);
        } else if(BN==128){
            CPA16(sptr(&Bs[s][boff]),   Bp + (size_t)k0*ldb);
            CPA16(sptr(&Bs[s][boff+8]), Bp + (size_t)k0*ldb + 8);
        } else {
            CPA16(sptr(&Bs[s][boff]),   Bp + (size_t)k0*ldb);
        }
    };

    auto compute = [&](int s){
        #pragma unroll
        for(int kk=0;kk<32;kk+=16){
            unsigned aR[WM][4], bR[WN][2];
            #pragma unroll
            for(int i=0;i<WM;i++){
                int r0 = (wm + i*16 + g)*SA + kk + q*2;
                int r1 = r0 + 8*SA;
                aR[i][0]=*(const unsigned*)&As[s][r0];   aR[i][1]=*(const unsigned*)&As[s][r1];
                aR[i][2]=*(const unsigned*)&As[s][r0+8]; aR[i][3]=*(const unsigned*)&As[s][r1+8];
            }
            #pragma unroll
            for(int j=0;j<WN;j++){
                int n = wn + j*8 + g;
                if(BNK){
                    int o = n*SBn + kk + q*2;
                    bR[j][0]=*(const unsigned*)&Bs[s][o]; bR[j][1]=*(const unsigned*)&Bs[s][o+8];
                } else {
                    const unsigned short* ph = (const unsigned short*)&Bs[s][(kk+q*2)*SBk + n];
                    bR[j][0] = (unsigned)ph[0]      | ((unsigned)ph[SBk]  <<16);
                    bR[j][1] = (unsigned)ph[8*SBk]  | ((unsigned)ph[9*SBk]<<16);
                }
            }
            #pragma unroll
            for(int i=0;i<WM;i++)
                #pragma unroll
                for(int j=0;j<WN;j++)
                    mma_f16(acc[i][j], aR[i], bR[j]);
        }
    };

    const int KT = K/32;
    stage(0, 0); CPCOMMIT;
    for(int s2=0;s2<KT;s2++){
        const int buf = s2&1;
        if(s2+1<KT){ stage(buf^1, (s2+1)*32); CPCOMMIT; cp_wait1(); }
        else cp_wait0();
        __syncthreads();
        compute(buf);
        __syncthreads();
    }
}

// ================== fused flash attention ==================
// Per (b,h): CTA owns 128 q-rows. Q resident; K/V streamed in 4 blocks of 128
// tokens (double-buffered). 8 warps partition m only (16 rows each). Online
// softmax; P fp16 straight into PV mma. Output ctx fp16.
#define SQ 72
#define FLASH_SMEM (5*128*SQ*2)   // Q + 2xK + 2xV halves -> 92160 bytes

__global__ __launch_bounds__(256,2) void flash_attn(){
    extern __shared__ h16 fs[];
    h16* Qs = fs;                   // 128*SQ
    h16* Ks = fs + 128*SQ;          // 2 bufs
    h16* Vs = fs + 3*128*SQ;        // 2 bufs
    const int bh = blockIdx.y, b = bh>>4, h = bh&15;
    const int m0 = blockIdx.x*128;
    const size_t qb = (size_t)b*NT*3*ND;
    const h16* Qg = g_qkvh + qb + h*DH;
    const h16* Kg = g_qkvh + qb + ND + h*DH;
    const h16* Vg = g_qkvh + qb + 2*ND + h*DH;
    const int tid=threadIdx.x, lane=tid&31, w=tid>>5;
    const int g=lane>>2, q=lane&3;

    // staging: 4 x 16B chunks per thread; chunk c=tid*4+i -> row=c>>3, col=(c&7)*8
    int srow[4], scc[4];
    #pragma unroll
    for(int i=0;i<4;i++){ int c=tid*4+i; srow[i]=c>>3; scc[i]=(c&7)*8; }

    #pragma unroll
    for(int i=0;i<4;i++){
        CPA16(sptr(&Qs[srow[i]*SQ+scc[i]]), Qg + (size_t)(m0+srow[i])*3*ND + scc[i]);
        CPA16(sptr(&Ks[srow[i]*SQ+scc[i]]), Kg + (size_t)srow[i]*3*ND + scc[i]);
        CPA16(sptr(&Vs[srow[i]*SQ+scc[i]]), Vg + (size_t)srow[i]*3*ND + scc[i]);
    }
    CPCOMMIT;

    float mrow[2] = {-1e30f,-1e30f};
    float lrow[2] = {0.f,0.f};
    float O[8][4] = {};

    for(int jb=0;jb<4;jb++){
        const int buf = jb&1;
        if(jb<3){
            const int nb=(jb+1)&1;
            #pragma unroll
            for(int i=0;i<4;i++){
                CPA16(sptr(&Ks[nb*128*SQ + srow[i]*SQ+scc[i]]), Kg + (size_t)((jb+1)*128+srow[i])*3*ND + scc[i]);
                CPA16(sptr(&Vs[nb*128*SQ + srow[i]*SQ+scc[i]]), Vg + (size_t)((jb+1)*128+srow[i])*3*ND + scc[i]);
            }
            CPCOMMIT; cp_wait1();
        } else cp_wait0();
        __syncthreads();
        const h16* Kb = Ks + buf*128*SQ;
        const h16* Vb = Vs + buf*128*SQ;

        #pragma unroll
        for(int hh=0; hh<2; hh++){
            // ---- S = Q @ Kb[hh half]^T ----
            float s[8][4] = {};
            #pragma unroll
            for(int kk=0;kk<4;kk++){
                unsigned a[4];
                int ab = (w*16+g)*SQ + kk*16 + q*2;
                a[0]=*(const unsigned*)&Qs[ab];   a[1]=*(const unsigned*)&Qs[ab+8*SQ];
                a[2]=*(const unsigned*)&Qs[ab+8]; a[3]=*(const unsigned*)&Qs[ab+8*SQ+8];
                #pragma unroll
                for(int j16=0;j16<8;j16++){
                    unsigned bfr[2];
                    int bb = (hh*64 + j16*8 + g)*SQ + kk*16 + q*2;
                    bfr[0]=*(const unsigned*)&Kb[bb]; bfr[1]=*(const unsigned*)&Kb[bb+8];
                    mma_f16(s[j16], a, bfr);
                }
            }
            // ---- online softmax ----
            float mx0=-1e30f, mx1=-1e30f;
            #pragma unroll
            for(int j16=0;j16<8;j16++){
                s[j16][0]*=0.125f; s[j16][1]*=0.125f; s[j16][2]*=0.125f; s[j16][3]*=0.125f;
                mx0 = fmaxf(mx0, fmaxf(s[j16][0], s[j16][1]));
                mx1 = fmaxf(mx1, fmaxf(s[j16][2], s[j16][3]));
            }
            mx0 = fmaxf(mx0, __shfl_xor_sync(0xffffffffu, mx0, 1));
            mx0 = fmaxf(mx0, __shfl_xor_sync(0xffffffffu, mx0, 2));
            mx1 = fmaxf(mx1, __shfl_xor_sync(0xffffffffu, mx1, 1));
            mx1 = fmaxf(mx1, __shfl_xor_sync(0xffffffffu, mx1, 2));
            float mn0 = fmaxf(mrow[0], mx0), mn1 = fmaxf(mrow[1], mx1);
            float sc0 = __expf(mrow[0]-mn0), sc1 = __expf(mrow[1]-mn1);
            float rs0=0.f, rs1=0.f;
            #pragma unroll
            for(int j16=0;j16<8;j16++){
                s[j16][0]=__expf(s[j16][0]-mn0); s[j16][1]=__expf(s[j16][1]-mn0);
                s[j16][2]=__expf(s[j16][2]-mn1); s[j16][3]=__expf(s[j16][3]-mn1);
                rs0 += s[j16][0]+s[j16][1]; rs1 += s[j16][2]+s[j16][3];
            }
            rs0 += __shfl_xor_sync(0xffffffffu, rs0, 1);
            rs0 += __shfl_xor_sync(0xffffffffu, rs0, 2);
            rs1 += __shfl_xor_sync(0xffffffffu, rs1, 1);
            rs1 += __shfl_xor_sync(0xffffffffu, rs1, 2);
            lrow[0] = lrow[0]*sc0 + rs0; lrow[1] = lrow[1]*sc1 + rs1;
            mrow[0]=mn0; mrow[1]=mn1;
            #pragma unroll
            for(int j2=0;j2<8;j2++){ O[j2][0]*=sc0; O[j2][1]*=sc0; O[j2][2]*=sc1; O[j2][3]*=sc1; }
            // ---- O += P @ Vb[hh half] ----
            #pragma unroll
            for(int kk2=0;kk2<4;kk2++){
                unsigned a[4];
                a[0]=round_pack(s[2*kk2][0],  s[2*kk2][1]);
                a[1]=round_pack(s[2*kk2][2],  s[2*kk2][3]);
                a[2]=round_pack(s[2*kk2+1][0],s[2*kk2+1][1]);
                a[3]=round_pack(s[2*kk2+1][2],s[2*kk2+1][3]);
                int t0 = hh*64 + kk2*16 + q*2;
                #pragma unroll
                for(int j2=0;j2<8;j2++){
                    int n = j2*8 + g;
                    const unsigned short* vp = (const unsigned short*)&Vb[t0*SQ + n];
                    unsigned bfr[2];
                    bfr[0] = (unsigned)vp[0]    | ((unsigned)vp[SQ]  <<16);
                    bfr[1] = (unsigned)vp[8*SQ] | ((unsigned)vp[9*SQ]<<16);
                    mma_f16(O[j2], a, bfr);
                }
            }
        }
        __syncthreads();
    }
    // ---- write ctx fp16 ----
    float inv0 = 1.f/lrow[0], inv1 = 1.f/lrow[1];
    int row0 = m0 + w*16 + g;
    size_t ob0 = (size_t)(b*NT + row0)*ND + h*DH;
    size_t ob1 = (size_t)(b*NT + row0 + 8)*ND + h*DH;
    #pragma unroll
    for(int j2=0;j2<8;j2++){
        int col = j2*8 + q*2;
        *(unsigned*)&g_ctxh[ob0+col] = round_pack(O[j2][0]*inv0, O[j2][1]*inv0);
        *(unsigned*)&g_ctxh[ob1+col] = round_pack(O[j2][2]*inv1, O[j2][3]*inv1);
    }
}

// ================== GEMM kernels ==================

__global__ __launch_bounds__(256,2) void tc_qkv(const float* __restrict__ bias){
    const int m0 = blockIdx.y*128, n0 = blockIdx.x*128;
    float acc[4][4][4] = {};
    core_h<128,2,4,4,4,false>(g_lnh + (size_t)m0*ND, ND, nullptr, g_wqkvh + n0, 3*ND, ND, acc);
    const int lane = threadIdx.x&31, w = threadIdx.x>>5;
    const int wm = (w&1)*64, wn = (w>>1)*32;
    const int g = lane>>2, q = lane&3;
    #pragma unroll
    for(int i=0;i<4;i++)
        #pragma unroll
        for(int j=0;j<4;j++)
            #pragma unroll
            for(int hh=0;hh<2;hh++){
                int row = m0 + wm + i*16 + g + hh*8;
                int col = n0 + wn + j*8 + q*2;
                *(unsigned*)&g_qkvh[(size_t)row*3*ND+col] =
                    round_pack(acc[i][j][hh*2] + bias[col], acc[i][j][hh*2+1] + bias[col+1]);
            }
}

__global__ __launch_bounds__(256,2) void tc_o(
    const float* __restrict__ bias, const float* __restrict__ res, float* __restrict__ out){
    const int m0 = blockIdx.y*128, n0 = blockIdx.x*128;
    float acc[4][4][4] = {};
    core_h<128,2,4,4,4,false>(g_ctxh + (size_t)m0*ND, ND, nullptr, g_woh + n0, ND, ND, acc);
    const int lane = threadIdx.x&31, w = threadIdx.x>>5;
    const int wm = (w&1)*64, wn = (w>>1)*32;
    const int g = lane>>2, q = lane&3;
    #pragma unroll
    for(int i=0;i<4;i++)
        #pragma unroll
        for(int j=0;j<4;j++)
            #pragma unroll
            for(int hh=0;hh<2;hh++){
                int row = m0 + wm + i*16 + g + hh*8;
                int col = n0 + wn + j*8 + q*2;
                float2 r = *(const float2*)&res[(size_t)row*ND+col];
                float2 o;
                o.x = acc[i][j][hh*2]   + bias[col]   + r.x;
                o.y = acc[i][j][hh*2+1] + bias[col+1] + r.y;
                *(float2*)&out[(size_t)row*ND+col] = o;
            }
}

__global__ __launch_bounds__(256,2) void tc_moe_gemm1(const float* __restrict__ b1){
    const int e = blockIdx.y >> 4;
    const int rt = blockIdx.y & 15;
    if(rt*128 >= g_count[e]) return;
    const int m0 = rt*128, n0 = blockIdx.x*128;
    float acc[4][4][4] = {};
    core_h<128,2,4,4,4,false>(g_lnh, ND, &g_slot_token[e*CAP + m0],
                              g_w1h + (size_t)e*ND*NF + n0, NF, ND, acc);
    const int lane = threadIdx.x&31, w = threadIdx.x>>5;
    const int wm = (w&1)*64, wn = (w>>1)*32;
    const int g = lane>>2, q = lane&3;
    #pragma unroll
    for(int i=0;i<4;i++)
        #pragma unroll
        for(int j=0;j<4;j++)
            #pragma unroll
            for(int hh=0;hh<2;hh++){
                int sl  = m0 + wm + i*16 + g + hh*8;
                int col = n0 + wn + j*8 + q*2;
                float v0 = gelu_tanh(acc[i][j][hh*2]   + b1[e*NF + col]);
                float v1 = gelu_tanh(acc[i][j][hh*2+1] + b1[e*NF + col+1]);
                *(unsigned*)&g_hidh[(size_t)(e*CAP+sl)*NF + col] = round_pack(v0, v1);
            }
}

__global__ __launch_bounds__(256,2) void tc_moe_gemm2(const float* __restrict__ b2, float* __restrict__ out){
    const int e = blockIdx.y >> 4;
    const int rt = blockIdx.y & 15;
    const int cnt = g_count[e];
    if(rt*128 >= cnt) return;
    const int m0 = rt*128, n0 = blockIdx.x*128;
    float acc[4][4][4] = {};
    core_h<128,2,4,4,4,false>(g_hidh + (size_t)(e*CAP + m0)*NF, NF, nullptr,
                              g_w2h + (size_t)e*NF*ND + n0, ND, NF, acc);
    const int lane = threadIdx.x&31, w = threadIdx.x>>5;
    const int wm = (w&1)*64, wn = (w>>1)*32;
    const int g = lane>>2, q = lane&3;
    #pragma unroll
    for(int i=0;i<4;i++)
        #pragma unroll
        for(int j=0;j<4;j++)
            #pragma unroll
            for(int hh=0;hh<2;hh++){
                int sl = m0 + wm + i*16 + g + hh*8;
                if(sl < cnt){
                    int tok = g_slot_token[e*CAP + sl];
                    float ws = g_slot_w[e*CAP + sl];
                    int col = n0 + wn + j*8 + q*2;
                    atomicAdd(&out[(size_t)tok*ND + col],   ws*(acc[i][j][hh*2]   + b2[e*ND + col]));
                    atomicAdd(&out[(size_t)tok*ND + col+1], ws*(acc[i][j][hh*2+1] + b2[e*ND + col+1]));
                }
            }
}

// ================== auxiliary kernels ==================

__global__ void conv_h_kernel(const float* __restrict__ src, h16* __restrict__ dst){
    size_t i = ((size_t)blockIdx.x*256 + threadIdx.x)*8;
    float4 a = *(const float4*)(src + i);
    float4 b = *(const float4*)(src + i + 4);
    *(uint4*)&dst[i] = make_uint4(round_pack(a.x,a.y), round_pack(a.z,a.w),
                                  round_pack(b.x,b.y), round_pack(b.z,b.w));
}

__global__ void ln_kernel(const float* __restrict__ x,
                          const float* __restrict__ w,
                          const float* __restrict__ b,
                          float* __restrict__ y, h16* __restrict__ yh)
{
    int row = blockIdx.x;
    int t = threadIdx.x;
    float4 v = *(const float4*)(x + (size_t)row*ND + t*4);
    float s = v.x+v.y+v.z+v.w;
    __shared__ float red[256];
    red[t] = s; __syncthreads();
    for(int o=128;o>0;o>>=1){ if(t<o) red[t]+=red[t+o]; __syncthreads(); }
    float mu = red[0]*(1.0f/ND);
    __syncthreads();
    float d0=v.x-mu, d1=v.y-mu, d2=v.z-mu, d3=v.w-mu;
    red[t] = d0*d0+d1*d1+d2*d2+d3*d3; __syncthreads();
    for(int o=128;o>0;o>>=1){ if(t<o) red[t]+=red[t+o]; __syncthreads(); }
    float rstd = rsqrtf(red[0]*(1.0f/ND) + 1e-5f);
    float4 wv = *(const float4*)(w + t*4);
    float4 bv = *(const float4*)(b + t*4);
    float4 o;
    o.x = d0*rstd*wv.x + bv.x;
    o.y = d1*rstd*wv.y + bv.y;
    o.z = d2*rstd*wv.z + bv.z;
    o.w = d3*rstd*wv.w + bv.w;
    *(float4*)(y + (size_t)row*ND + t*4) = o;
    *(uint2*)&yh[(size_t)row*ND + t*4] = make_uint2(round_pack(o.x,o.y), round_pack(o.z,o.w));
}

__global__ void moe_reset_kernel()
{
    int i = blockIdx.x*256 + threadIdx.x;
    if(i < NSLOT) g_slot_token[i] = -1;
    if(i < NE) g_count[i] = 0;
}

__global__ void gate_kernel(const float* __restrict__ wg)
{
    int token = blockIdx.x*8 + (threadIdx.x>>5);
    int lane = threadIdx.x & 31;
    const float* t = g_ln + (size_t)token*ND;
    float acc[NE] = {};
    for(int d=lane; d<ND; d+=32){
        float td = t[d];
        const float* w = wg + d*NE;
        #pragma unroll
        for(int e=0;e<NE;e++) acc[e] += td*w[e];
    }
    #pragma unroll
    for(int e=0;e<NE;e++)
        #pragma unroll
        for(int o=16;o>0;o>>=1) acc[e] += __shfl_xor_sync(0xffffffffu, acc[e], o);
    if(lane==0){
        float mx = -1e30f;
        #pragma unroll
        for(int e=0;e<NE;e++) mx = fmaxf(mx, acc[e]);
        float p[NE], s=0.f;
        #pragma unroll
        for(int e=0;e<NE;e++){ p[e] = expf(acc[e]-mx); s += p[e]; }
        float inv = 1.0f/s;
        #pragma unroll
        for(int e=0;e<NE;e++) p[e] *= inv;
        int e0 = 0;
        #pragma unroll
        for(int e=1;e<NE;e++) if(p[e] > p[e0]) e0 = e;
        int e1 = (e0==0) ? 1 : 0;
        #pragma unroll
        for(int e=0;e<NE;e++) if(e!=e0 && p[e] > p[e1]) e1 = e;
        float w0 = p[e0], w1 = p[e1];
        float rn = 1.0f/(w0+w1);
        w0 *= rn; w1 *= rn;
        int p0 = atomicAdd(&g_count[e0], 1);
        g_slot_token[e0*CAP + p0] = token; g_slot_w[e0*CAP + p0] = w0;
        int p1 = atomicAdd(&g_count[e1], 1);
        g_slot_token[e1*CAP + p1] = token; g_slot_w[e1*CAP + p1] = w1;
    }
}

// ================== launch ==================
extern "C" void kernel_launch(void* const* d_in, const int* in_sizes, int n_in,
                              void* d_out, int out_size)
{
    const float* x    = (const float*)d_in[0];
    const float* ln1w = (const float*)d_in[1];
    const float* ln1b = (const float*)d_in[2];
    const float* ln2w = (const float*)d_in[3];
    const float* ln2b = (const float*)d_in[4];
    const float* wqkv = (const float*)d_in[5];
    const float* bqkv = (const float*)d_in[6];
    const float* wo   = (const float*)d_in[7];
    const float* bo   = (const float*)d_in[8];
    const float* wg   = (const float*)d_in[9];
    const float* w1   = (const float*)d_in[10];
    const float* b1   = (const float*)d_in[11];
    const float* w2   = (const float*)d_in[12];
    const float* b2   = (const float*)d_in[13];
    float* out = (float*)d_out;

    float *p_ln;
    h16 *p_lnh, *p_wqkvh, *p_woh, *p_w1h, *p_w2h;
    cudaGetSymbolAddress((void**)&p_ln,    g_ln);
    cudaGetSymbolAddress((void**)&p_lnh,   g_lnh);
    cudaGetSymbolAddress((void**)&p_wqkvh, g_wqkvh);
    cudaGetSymbolAddress((void**)&p_woh,   g_woh);
    cudaGetSymbolAddress((void**)&p_w1h,   g_w1h);
    cudaGetSymbolAddress((void**)&p_w2h,   g_w2h);

    cudaFuncSetAttribute(flash_attn, cudaFuncAttributeMaxDynamicSharedMemorySize, FLASH_SMEM);

    // weight fp32->fp16 (once per call)
    conv_h_kernel<<<3*ND*ND/2048, 256>>>(wqkv, p_wqkvh);
    conv_h_kernel<<<ND*ND/2048,   256>>>(wo,   p_woh);
    conv_h_kernel<<<NE*ND*NF/2048,256>>>(w1,   p_w1h);
    conv_h_kernel<<<NE*NF*ND/2048,256>>>(w2,   p_w2h);

    ln_kernel<<<NTOK, 256>>>(x, ln1w, ln1b, p_ln, p_lnh);
    tc_qkv<<<dim3(3*ND/128, NTOK/128), 256>>>(bqkv);
    flash_attn<<<dim3(NT/128, NB*NHEAD), 256, FLASH_SMEM>>>();
    tc_o<<<dim3(ND/128, NTOK/128), 256>>>(bo, x, out);
    ln_kernel<<<NTOK, 256>>>(out, ln2w, ln2b, p_ln, p_lnh);
    moe_reset_kernel<<<NSLOT/256, 256>>>();
    gate_kernel<<<NTOK/8, 256>>>(wg);
    tc_moe_gemm1<<<dim3(NF/128, NE*16), 256>>>(b1);
    tc_moe_gemm2<<<dim3(ND/128, NE*16), 256>>>(b2, out);
}

// round 12
// speedup vs baseline: 3.4609x; 1.2248x over previous
#include <cuda_runtime.h>
#include <cuda_fp16.h>
#include <math.h>

#define NB 4
#define NT 512
#define ND 1024
#define NF 4096
#define NE 8
#define NHEAD 16
#define DH 64
#define NTOK (NB*NT)          // 2048
#define CAP 2048
#define NSLOT (NE*CAP)
typedef __half h16;

// ---- static scratch ----
__device__ float g_ln[NTOK*ND];                          // fp32 ln (gate input)
__device__ h16 g_lnh[NTOK*ND];
__device__ h16 g_qkvh[(size_t)NTOK*3*ND];
__device__ h16 g_ctxh[NTOK*ND];
__device__ h16 g_hidh[(size_t)NSLOT*NF];
__device__ h16 g_wqkvh[3*ND*ND];
__device__ h16 g_woh[ND*ND];
__device__ h16 g_w1h[(size_t)NE*ND*NF];
__device__ h16 g_w2h[(size_t)NE*NF*ND];
__device__ int   g_slot_token[NSLOT];
__device__ float g_slot_w[NSLOT];
__device__ int   g_count[NE];

__device__ __forceinline__ float gelu_tanh(float x){
    float x3 = x*x*x;
    return 0.5f*x*(1.0f + tanhf(0.7978845608028654f*(x + 0.044715f*x3)));
}
__device__ __forceinline__ unsigned round_pack(float x0, float x1){
    return ((unsigned)__half_as_ushort(__float2half_rn(x1))<<16)
         |  (unsigned)__half_as_ushort(__float2half_rn(x0));
}
__device__ __forceinline__ unsigned sptr(const void* p){
    return (unsigned)__cvta_generic_to_shared(p);
}
#define CPA16(dst,src)    asm volatile("cp.async.cg.shared.global [%0],[%1],16;\n"::"r"(dst),"l"(src):"memory")
#define CPA16Z(dst,src,z) asm volatile("cp.async.cg.shared.global [%0],[%1],16,%2;\n"::"r"(dst),"l"(src),"r"(z):"memory")
#define CPCOMMIT          asm volatile("cp.async.commit_group;\n":::"memory")
__device__ __forceinline__ void cp_wait0(){ asm volatile("cp.async.wait_group 0;\n":::"memory"); }
__device__ __forceinline__ void cp_wait1(){ asm volatile("cp.async.wait_group 1;\n":::"memory"); }

__device__ __forceinline__ void ldsm4(unsigned* r, unsigned a){
    asm volatile("ldmatrix.sync.aligned.m8n8.x4.shared.b16 {%0,%1,%2,%3},[%4];\n"
        :"=r"(r[0]),"=r"(r[1]),"=r"(r[2]),"=r"(r[3]):"r"(a));
}
__device__ __forceinline__ void ldsm4t(unsigned* r, unsigned a){
    asm volatile("ldmatrix.sync.aligned.m8n8.x4.trans.shared.b16 {%0,%1,%2,%3},[%4];\n"
        :"=r"(r[0]),"=r"(r[1]),"=r"(r[2]),"=r"(r[3]):"r"(a));
}
__device__ __forceinline__ void mma_f16(float* c, const unsigned* a, const unsigned* b){
    asm volatile("mma.sync.aligned.m16n8k16.row.col.f32.f16.f16.f32 "
        "{%0,%1,%2,%3}, {%4,%5,%6,%7}, {%8,%9}, {%0,%1,%2,%3};\n"
        : "+f"(c[0]),"+f"(c[1]),"+f"(c[2]),"+f"(c[3])
        : "r"(a[0]),"r"(a[1]),"r"(a[2]),"r"(a[3]), "r"(b[0]),"r"(b[1]));
}

// ================== fp16 GEMM core v3: ldmatrix + 3-stage cp.async ==================
// 128x128 tile, BK=32, 256 threads (8 warps, 2m x 4n, warp tile 64x32).
// A: fp16 row-major [M,K] (pre-offset to block row, or rmap gather).
// B: fp16 k-major [K,N] (pre-offset by n0).
#define GEMM_SMEM (3*(128*40 + 32*136)*2)   // 56832 bytes

__device__ __forceinline__ void core_h(
    const h16* __restrict__ A, int lda, const int* __restrict__ rmap,
    const h16* __restrict__ Bm, int ldb, int K,
    float acc[4][4][4])
{
    constexpr int SA = 40;    // A smem row stride (halves)
    constexpr int SB = 136;   // B smem row stride (halves)
    extern __shared__ h16 ds[];
    h16* As = ds;                   // 3 stages of 128*SA
    h16* Bs = ds + 3*128*SA;        // 3 stages of 32*SB

    const int tid=threadIdx.x, lane=tid&31, w=tid>>5;
    const int wm=(w&1)*64, wn=(w>>1)*32;
    const int lt=lane>>3, lr=lane&7;

    // A staging: row = tid>>1, two 16B chunks at halves (tid&1)*16, +8
    const int ar = tid>>1, ak = (tid&1)*16;
    const h16* Ap;
    unsigned az = 16;
    if(rmap){ int tok=rmap[ar]; if(tok<0){ az=0; tok=0; } Ap = A + (size_t)tok*lda + ak; }
    else      Ap = A + (size_t)ar*lda + ak;
    const unsigned aoff = ar*SA + ak;

    // B staging: row(k) = tid>>3, col = (tid&7)*16, two chunks
    const int br = tid>>3, bc = (tid&7)*16;
    const h16* Bp = Bm + (size_t)br*ldb + bc;
    const unsigned boff = br*SB + bc;

    auto stage = [&](int s, int k0){
        h16* Ad = As + s*128*SA;
        h16* Bd = Bs + s*32*SB;
        if(rmap){
            CPA16Z(sptr(&Ad[aoff]),   Ap + k0,     az);
            CPA16Z(sptr(&Ad[aoff+8]), Ap + k0 + 8, az);
        } else {
            CPA16(sptr(&Ad[aoff]),   Ap + k0);
            CPA16(sptr(&Ad[aoff+8]), Ap + k0 + 8);
        }
        CPA16(sptr(&Bd[boff]),   Bp + (size_t)k0*ldb);
        CPA16(sptr(&Bd[boff+8]), Bp + (size_t)k0*ldb + 8);
    };

    auto compute = [&](int s){
        h16* Ad = As + s*128*SA;
        h16* Bd = Bs + s*32*SB;
        #pragma unroll
        for(int kk=0;kk<32;kk+=16){
            unsigned aR[4][4], bR[4][2];
            #pragma unroll
            for(int i=0;i<4;i++){
                unsigned off = (unsigned)((wm + i*16 + (lt&1)*8 + lr)*SA + kk + (lt>>1)*8);
                ldsm4(aR[i], sptr(Ad + off));
            }
            #pragma unroll
            for(int jp=0;jp<2;jp++){
                unsigned off = (unsigned)((kk + (lt&1)*8 + lr)*SB + wn + jp*16 + (lt>>1)*8);
                unsigned r[4];
                ldsm4t(r, sptr(Bd + off));
                bR[jp*2][0]=r[0];   bR[jp*2][1]=r[1];
                bR[jp*2+1][0]=r[2]; bR[jp*2+1][1]=r[3];
            }
            #pragma unroll
            for(int i=0;i<4;i++)
                #pragma unroll
                for(int j=0;j<4;j++)
                    mma_f16(acc[i][j], aR[i], bR[j]);
        }
    };

    const int KT = K/32;
    stage(0, 0);  CPCOMMIT;
    stage(1, 32); CPCOMMIT;
    for(int s=0;s<KT;s++){
        if(s+2<KT) cp_wait1(); else cp_wait0();
        __syncthreads();
        if(s+2<KT){ stage((s+2)%3, (s+2)*32); CPCOMMIT; }
        compute(s%3);
    }
}

// ================== fused flash attention (unchanged from round 10) ==================
#define SQ 72
#define FLASH_SMEM (5*128*SQ*2)   // 92160 bytes

__global__ __launch_bounds__(256,2) void flash_attn(){
    extern __shared__ h16 fs[];
    h16* Qs = fs;
    h16* Ks = fs + 128*SQ;
    h16* Vs = fs + 3*128*SQ;
    const int bh = blockIdx.y, b = bh>>4, h = bh&15;
    const int m0 = blockIdx.x*128;
    const size_t qb = (size_t)b*NT*3*ND;
    const h16* Qg = g_qkvh + qb + h*DH;
    const h16* Kg = g_qkvh + qb + ND + h*DH;
    const h16* Vg = g_qkvh + qb + 2*ND + h*DH;
    const int tid=threadIdx.x, lane=tid&31, w=tid>>5;
    const int g=lane>>2, q=lane&3;

    int srow[4], scc[4];
    #pragma unroll
    for(int i=0;i<4;i++){ int c=tid*4+i; srow[i]=c>>3; scc[i]=(c&7)*8; }

    #pragma unroll
    for(int i=0;i<4;i++){
        CPA16(sptr(&Qs[srow[i]*SQ+scc[i]]), Qg + (size_t)(m0+srow[i])*3*ND + scc[i]);
        CPA16(sptr(&Ks[srow[i]*SQ+scc[i]]), Kg + (size_t)srow[i]*3*ND + scc[i]);
        CPA16(sptr(&Vs[srow[i]*SQ+scc[i]]), Vg + (size_t)srow[i]*3*ND + scc[i]);
    }
    CPCOMMIT;

    float mrow[2] = {-1e30f,-1e30f};
    float lrow[2] = {0.f,0.f};
    float O[8][4] = {};

    for(int jb=0;jb<4;jb++){
        const int buf = jb&1;
        if(jb<3){
            const int nb=(jb+1)&1;
            #pragma unroll
            for(int i=0;i<4;i++){
                CPA16(sptr(&Ks[nb*128*SQ + srow[i]*SQ+scc[i]]), Kg + (size_t)((jb+1)*128+srow[i])*3*ND + scc[i]);
                CPA16(sptr(&Vs[nb*128*SQ + srow[i]*SQ+scc[i]]), Vg + (size_t)((jb+1)*128+srow[i])*3*ND + scc[i]);
            }
            CPCOMMIT; cp_wait1();
        } else cp_wait0();
        __syncthreads();
        const h16* Kb = Ks + buf*128*SQ;
        const h16* Vb = Vs + buf*128*SQ;

        #pragma unroll
        for(int hh=0; hh<2; hh++){
            float s[8][4] = {};
            #pragma unroll
            for(int kk=0;kk<4;kk++){
                unsigned a[4];
                int ab = (w*16+g)*SQ + kk*16 + q*2;
                a[0]=*(const unsigned*)&Qs[ab];   a[1]=*(const unsigned*)&Qs[ab+8*SQ];
                a[2]=*(const unsigned*)&Qs[ab+8]; a[3]=*(const unsigned*)&Qs[ab+8*SQ+8];
                #pragma unroll
                for(int j16=0;j16<8;j16++){
                    unsigned bfr[2];
                    int bb = (hh*64 + j16*8 + g)*SQ + kk*16 + q*2;
                    bfr[0]=*(const unsigned*)&Kb[bb]; bfr[1]=*(const unsigned*)&Kb[bb+8];
                    mma_f16(s[j16], a, bfr);
                }
            }
            float mx0=-1e30f, mx1=-1e30f;
            #pragma unroll
            for(int j16=0;j16<8;j16++){
                s[j16][0]*=0.125f; s[j16][1]*=0.125f; s[j16][2]*=0.125f; s[j16][3]*=0.125f;
                mx0 = fmaxf(mx0, fmaxf(s[j16][0], s[j16][1]));
                mx1 = fmaxf(mx1, fmaxf(s[j16][2], s[j16][3]));
            }
            mx0 = fmaxf(mx0, __shfl_xor_sync(0xffffffffu, mx0, 1));
            mx0 = fmaxf(mx0, __shfl_xor_sync(0xffffffffu, mx0, 2));
            mx1 = fmaxf(mx1, __shfl_xor_sync(0xffffffffu, mx1, 1));
            mx1 = fmaxf(mx1, __shfl_xor_sync(0xffffffffu, mx1, 2));
            float mn0 = fmaxf(mrow[0], mx0), mn1 = fmaxf(mrow[1], mx1);
            float sc0 = __expf(mrow[0]-mn0), sc1 = __expf(mrow[1]-mn1);
            float rs0=0.f, rs1=0.f;
            #pragma unroll
            for(int j16=0;j16<8;j16++){
                s[j16][0]=__expf(s[j16][0]-mn0); s[j16][1]=__expf(s[j16][1]-mn0);
                s[j16][2]=__expf(s[j16][2]-mn1); s[j16][3]=__expf(s[j16][3]-mn1);
                rs0 += s[j16][0]+s[j16][1]; rs1 += s[j16][2]+s[j16][3];
            }
            rs0 += __shfl_xor_sync(0xffffffffu, rs0, 1);
            rs0 += __shfl_xor_sync(0xffffffffu, rs0, 2);
            rs1 += __shfl_xor_sync(0xffffffffu, rs1, 1);
            rs1 += __shfl_xor_sync(0xffffffffu, rs1, 2);
            lrow[0] = lrow[0]*sc0 + rs0; lrow[1] = lrow[1]*sc1 + rs1;
            mrow[0]=mn0; mrow[1]=mn1;
            #pragma unroll
            for(int j2=0;j2<8;j2++){ O[j2][0]*=sc0; O[j2][1]*=sc0; O[j2][2]*=sc1; O[j2][3]*=sc1; }
            #pragma unroll
            for(int kk2=0;kk2<4;kk2++){
                unsigned a[4];
                a[0]=round_pack(s[2*kk2][0],  s[2*kk2][1]);
                a[1]=round_pack(s[2*kk2][2],  s[2*kk2][3]);
                a[2]=round_pack(s[2*kk2+1][0],s[2*kk2+1][1]);
                a[3]=round_pack(s[2*kk2+1][2],s[2*kk2+1][3]);
                int t0 = hh*64 + kk2*16 + q*2;
                #pragma unroll
                for(int j2=0;j2<8;j2++){
                    int n = j2*8 + g;
                    const unsigned short* vp = (const unsigned short*)&Vb[t0*SQ + n];
                    unsigned bfr[2];
                    bfr[0] = (unsigned)vp[0]    | ((unsigned)vp[SQ]  <<16);
                    bfr[1] = (unsigned)vp[8*SQ] | ((unsigned)vp[9*SQ]<<16);
                    mma_f16(O[j2], a, bfr);
                }
            }
        }
        __syncthreads();
    }
    float inv0 = 1.f/lrow[0], inv1 = 1.f/lrow[1];
    int row0 = m0 + w*16 + g;
    size_t ob0 = (size_t)(b*NT + row0)*ND + h*DH;
    size_t ob1 = (size_t)(b*NT + row0 + 8)*ND + h*DH;
    #pragma unroll
    for(int j2=0;j2<8;j2++){
        int col = j2*8 + q*2;
        *(unsigned*)&g_ctxh[ob0+col] = round_pack(O[j2][0]*inv0, O[j2][1]*inv0);
        *(unsigned*)&g_ctxh[ob1+col] = round_pack(O[j2][2]*inv1, O[j2][3]*inv1);
    }
}

// ================== GEMM kernels ==================

__global__ __launch_bounds__(256,2) void tc_qkv(const float* __restrict__ bias){
    const int m0 = blockIdx.y*128, n0 = blockIdx.x*128;
    float acc[4][4][4] = {};
    core_h(g_lnh + (size_t)m0*ND, ND, nullptr, g_wqkvh + n0, 3*ND, ND, acc);
    const int lane = threadIdx.x&31, w = threadIdx.x>>5;
    const int wm = (w&1)*64, wn = (w>>1)*32;
    const int g = lane>>2, q = lane&3;
    #pragma unroll
    for(int i=0;i<4;i++)
        #pragma unroll
        for(int j=0;j<4;j++)
            #pragma unroll
            for(int hh=0;hh<2;hh++){
                int row = m0 + wm + i*16 + g + hh*8;
                int col = n0 + wn + j*8 + q*2;
                *(unsigned*)&g_qkvh[(size_t)row*3*ND+col] =
                    round_pack(acc[i][j][hh*2] + bias[col], acc[i][j][hh*2+1] + bias[col+1]);
            }
}

__global__ __launch_bounds__(256,2) void tc_o(
    const float* __restrict__ bias, const float* __restrict__ res, float* __restrict__ out){
    const int m0 = blockIdx.y*128, n0 = blockIdx.x*128;
    float acc[4][4][4] = {};
    core_h(g_ctxh + (size_t)m0*ND, ND, nullptr, g_woh + n0, ND, ND, acc);
    const int lane = threadIdx.x&31, w = threadIdx.x>>5;
    const int wm = (w&1)*64, wn = (w>>1)*32;
    const int g = lane>>2, q = lane&3;
    #pragma unroll
    for(int i=0;i<4;i++)
        #pragma unroll
        for(int j=0;j<4;j++)
            #pragma unroll
            for(int hh=0;hh<2;hh++){
                int row = m0 + wm + i*16 + g + hh*8;
                int col = n0 + wn + j*8 + q*2;
                float2 r = *(const float2*)&res[(size_t)row*ND+col];
                float2 o;
                o.x = acc[i][j][hh*2]   + bias[col]   + r.x;
                o.y = acc[i][j][hh*2+1] + bias[col+1] + r.y;
                *(float2*)&out[(size_t)row*ND+col] = o;
            }
}

__global__ __launch_bounds__(256,2) void tc_moe_gemm1(const float* __restrict__ b1){
    const int e = blockIdx.y >> 4;
    const int rt = blockIdx.y & 15;
    if(rt*128 >= g_count[e]) return;
    const int m0 = rt*128, n0 = blockIdx.x*128;
    float acc[4][4][4] = {};
    core_h(g_lnh, ND, &g_slot_token[e*CAP + m0], g_w1h + (size_t)e*ND*NF + n0, NF, ND, acc);
    const int lane = threadIdx.x&31, w = threadIdx.x>>5;
    const int wm = (w&1)*64, wn = (w>>1)*32;
    const int g = lane>>2, q = lane&3;
    #pragma unroll
    for(int i=0;i<4;i++)
        #pragma unroll
        for(int j=0;j<4;j++)
            #pragma unroll
            for(int hh=0;hh<2;hh++){
                int sl  = m0 + wm + i*16 + g + hh*8;
                int col = n0 + wn + j*8 + q*2;
                float v0 = gelu_tanh(acc[i][j][hh*2]   + b1[e*NF + col]);
                float v1 = gelu_tanh(acc[i][j][hh*2+1] + b1[e*NF + col+1]);
                *(unsigned*)&g_hidh[(size_t)(e*CAP+sl)*NF + col] = round_pack(v0, v1);
            }
}

__global__ __launch_bounds__(256,2) void tc_moe_gemm2(const float* __restrict__ b2, float* __restrict__ out){
    const int e = blockIdx.y >> 4;
    const int rt = blockIdx.y & 15;
    const int cnt = g_count[e];
    if(rt*128 >= cnt) return;
    const int m0 = rt*128, n0 = blockIdx.x*128;
    float acc[4][4][4] = {};
    core_h(g_hidh + (size_t)(e*CAP + m0)*NF, NF, nullptr, g_w2h + (size_t)e*NF*ND + n0, ND, NF, acc);
    const int lane = threadIdx.x&31, w = threadIdx.x>>5;
    const int wm = (w&1)*64, wn = (w>>1)*32;
    const int g = lane>>2, q = lane&3;
    #pragma unroll
    for(int i=0;i<4;i++)
        #pragma unroll
        for(int j=0;j<4;j++)
            #pragma unroll
            for(int hh=0;hh<2;hh++){
                int sl = m0 + wm + i*16 + g + hh*8;
                if(sl < cnt){
                    int tok = g_slot_token[e*CAP + sl];
                    float ws = g_slot_w[e*CAP + sl];
                    int col = n0 + wn + j*8 + q*2;
                    atomicAdd(&out[(size_t)tok*ND + col],   ws*(acc[i][j][hh*2]   + b2[e*ND + col]));
                    atomicAdd(&out[(size_t)tok*ND + col+1], ws*(acc[i][j][hh*2+1] + b2[e*ND + col+1]));
                }
            }
}

// ================== auxiliary kernels ==================

__global__ void conv_h_kernel(const float* __restrict__ src, h16* __restrict__ dst){
    size_t i = ((size_t)blockIdx.x*256 + threadIdx.x)*8;
    float4 a = *(const float4*)(src + i);
    float4 b = *(const float4*)(src + i + 4);
    *(uint4*)&dst[i] = make_uint4(round_pack(a.x,a.y), round_pack(a.z,a.w),
                                  round_pack(b.x,b.y), round_pack(b.z,b.w));
}

__global__ void ln_kernel(const float* __restrict__ x,
                          const float* __restrict__ w,
                          const float* __restrict__ b,
                          float* __restrict__ y, h16* __restrict__ yh)
{
    int row = blockIdx.x;
    int t = threadIdx.x;
    float4 v = *(const float4*)(x + (size_t)row*ND + t*4);
    float s = v.x+v.y+v.z+v.w;
    __shared__ float red[256];
    red[t] = s; __syncthreads();
    for(int o=128;o>0;o>>=1){ if(t<o) red[t]+=red[t+o]; __syncthreads(); }
    float mu = red[0]*(1.0f/ND);
    __syncthreads();
    float d0=v.x-mu, d1=v.y-mu, d2=v.z-mu, d3=v.w-mu;
    red[t] = d0*d0+d1*d1+d2*d2+d3*d3; __syncthreads();
    for(int o=128;o>0;o>>=1){ if(t<o) red[t]+=red[t+o]; __syncthreads(); }
    float rstd = rsqrtf(red[0]*(1.0f/ND) + 1e-5f);
    float4 wv = *(const float4*)(w + t*4);
    float4 bv = *(const float4*)(b + t*4);
    float4 o;
    o.x = d0*rstd*wv.x + bv.x;
    o.y = d1*rstd*wv.y + bv.y;
    o.z = d2*rstd*wv.z + bv.z;
    o.w = d3*rstd*wv.w + bv.w;
    *(float4*)(y + (size_t)row*ND + t*4) = o;
    *(uint2*)&yh[(size_t)row*ND + t*4] = make_uint2(round_pack(o.x,o.y), round_pack(o.z,o.w));
}

__global__ void moe_reset_kernel()
{
    int i = blockIdx.x*256 + threadIdx.x;
    if(i < NSLOT) g_slot_token[i] = -1;
    if(i < NE) g_count[i] = 0;
}

__global__ void gate_kernel(const float* __restrict__ wg)
{
    int token = blockIdx.x*8 + (threadIdx.x>>5);
    int lane = threadIdx.x & 31;
    const float* t = g_ln + (size_t)token*ND;
    float acc[NE] = {};
    for(int d=lane; d<ND; d+=32){
        float td = t[d];
        const float* w = wg + d*NE;
        #pragma unroll
        for(int e=0;e<NE;e++) acc[e] += td*w[e];
    }
    #pragma unroll
    for(int e=0;e<NE;e++)
        #pragma unroll
        for(int o=16;o>0;o>>=1) acc[e] += __shfl_xor_sync(0xffffffffu, acc[e], o);
    if(lane==0){
        float mx = -1e30f;
        #pragma unroll
        for(int e=0;e<NE;e++) mx = fmaxf(mx, acc[e]);
        float p[NE], s=0.f;
        #pragma unroll
        for(int e=0;e<NE;e++){ p[e] = expf(acc[e]-mx); s += p[e]; }
        float inv = 1.0f/s;
        #pragma unroll
        for(int e=0;e<NE;e++) p[e] *= inv;
        int e0 = 0;
        #pragma unroll
        for(int e=1;e<NE;e++) if(p[e] > p[e0]) e0 = e;
        int e1 = (e0==0) ? 1 : 0;
        #pragma unroll
        for(int e=0;e<NE;e++) if(e!=e0 && p[e] > p[e1]) e1 = e;
        float w0 = p[e0], w1 = p[e1];
        float rn = 1.0f/(w0+w1);
        w0 *= rn; w1 *= rn;
        int p0 = atomicAdd(&g_count[e0], 1);
        g_slot_token[e0*CAP + p0] = token; g_slot_w[e0*CAP + p0] = w0;
        int p1 = atomicAdd(&g_count[e1], 1);
        g_slot_token[e1*CAP + p1] = token; g_slot_w[e1*CAP + p1] = w1;
    }
}

// ================== launch ==================
extern "C" void kernel_launch(void* const* d_in, const int* in_sizes, int n_in,
                              void* d_out, int out_size)
{
    const float* x    = (const float*)d_in[0];
    const float* ln1w = (const float*)d_in[1];
    const float* ln1b = (const float*)d_in[2];
    const float* ln2w = (const float*)d_in[3];
    const float* ln2b = (const float*)d_in[4];
    const float* wqkv = (const float*)d_in[5];
    const float* bqkv = (const float*)d_in[6];
    const float* wo   = (const float*)d_in[7];
    const float* bo   = (const float*)d_in[8];
    const float* wg   = (const float*)d_in[9];
    const float* w1   = (const float*)d_in[10];
    const float* b1   = (const float*)d_in[11];
    const float* w2   = (const float*)d_in[12];
    const float* b2   = (const float*)d_in[13];
    float* out = (float*)d_out;

    float *p_ln;
    h16 *p_lnh, *p_wqkvh, *p_woh, *p_w1h, *p_w2h;
    cudaGetSymbolAddress((void**)&p_ln,    g_ln);
    cudaGetSymbolAddress((void**)&p_lnh,   g_lnh);
    cudaGetSymbolAddress((void**)&p_wqkvh, g_wqkvh);
    cudaGetSymbolAddress((void**)&p_woh,   g_woh);
    cudaGetSymbolAddress((void**)&p_w1h,   g_w1h);
    cudaGetSymbolAddress((void**)&p_w2h,   g_w2h);

    cudaFuncSetAttribute(flash_attn,   cudaFuncAttributeMaxDynamicSharedMemorySize, FLASH_SMEM);
    cudaFuncSetAttribute(tc_qkv,       cudaFuncAttributeMaxDynamicSharedMemorySize, GEMM_SMEM);
    cudaFuncSetAttribute(tc_o,         cudaFuncAttributeMaxDynamicSharedMemorySize, GEMM_SMEM);
    cudaFuncSetAttribute(tc_moe_gemm1, cudaFuncAttributeMaxDynamicSharedMemorySize, GEMM_SMEM);
    cudaFuncSetAttribute(tc_moe_gemm2, cudaFuncAttributeMaxDynamicSharedMemorySize, GEMM_SMEM);

    // weight fp32->fp16 (once per call)
    conv_h_kernel<<<3*ND*ND/2048, 256>>>(wqkv, p_wqkvh);
    conv_h_kernel<<<ND*ND/2048,   256>>>(wo,   p_woh);
    conv_h_kernel<<<NE*ND*NF/2048,256>>>(w1,   p_w1h);
    conv_h_kernel<<<NE*NF*ND/2048,256>>>(w2,   p_w2h);

    ln_kernel<<<NTOK, 256>>>(x, ln1w, ln1b, p_ln, p_lnh);
    tc_qkv<<<dim3(3*ND/128, NTOK/128), 256, GEMM_SMEM>>>(bqkv);
    flash_attn<<<dim3(NT/128, NB*NHEAD), 256, FLASH_SMEM>>>();
    tc_o<<<dim3(ND/128, NTOK/128), 256, GEMM_SMEM>>>(bo, x, out);
    ln_kernel<<<NTOK, 256>>>(out, ln2w, ln2b, p_ln, p_lnh);
    moe_reset_kernel<<<NSLOT/256, 256>>>();
    gate_kernel<<<NTOK/8, 256>>>(wg);
    tc_moe_gemm1<<<dim3(NF/128, NE*16), 256, GEMM_SMEM>>>(b1);
    tc_moe_gemm2<<<dim3(ND/128, NE*16), 256, GEMM_SMEM>>>(b2, out);
}